// round 1
// baseline (speedup 1.0000x reference)
#include <cuda_runtime.h>
#include <math.h>

#define Bz 4
#define T 2048
#define C 1024
#define NH 16
#define HS 64
#define M (Bz*T)

// Scratch (allocation-free rule: __device__ globals)
__device__ float g_q[Bz*NH*T*HS];   // [B,NH,T,HS]
__device__ float g_k[Bz*NH*T*HS];
__device__ float g_v[Bz*NH*T*HS];
__device__ float g_att[M*C];        // [B,T,C]

// ---------------------------------------------------------------------------
// GEMM: out = X[M,C] @ W[C,C] + bias, 64x64x16 tiles, 256 threads, 4x4/thread
// WHICH: 0 -> g_q (RoPE + head layout), 1 -> g_k (RoPE + head layout),
//        2 -> g_v (head layout), 3 -> X=g_att, out=param (plain layout)
// ---------------------------------------------------------------------------
template<int WHICH>
__global__ __launch_bounds__(256)
void gemm_kernel(const float* __restrict__ Xin,
                 const float* __restrict__ W,
                 const float* __restrict__ bias,
                 float* __restrict__ outp)
{
    __shared__ float Xs[64][17];
    __shared__ float Ws[16][64];

    const float* X = (WHICH == 3) ? g_att : Xin;
    float* out;
    if (WHICH == 0)      out = g_q;
    else if (WHICH == 1) out = g_k;
    else if (WHICH == 2) out = g_v;
    else                 out = outp;

    const int tid = threadIdx.x;
    const int tx = tid & 15;
    const int ty = tid >> 4;
    const int tileM = blockIdx.y * 64;
    const int tileN = blockIdx.x * 64;

    // global->smem load coords
    const int xr = tid >> 2;          // 0..63
    const int xc = (tid & 3) * 4;     // 0..12
    const int wr = tid >> 4;          // 0..15
    const int wc = (tid & 15) * 4;    // 0..60

    float acc[4][4] = {};

    for (int k0 = 0; k0 < C; k0 += 16) {
        float4 xv = *(const float4*)&X[(size_t)(tileM + xr) * C + k0 + xc];
        Xs[xr][xc + 0] = xv.x;
        Xs[xr][xc + 1] = xv.y;
        Xs[xr][xc + 2] = xv.z;
        Xs[xr][xc + 3] = xv.w;
        float4 wv = *(const float4*)&W[(size_t)(k0 + wr) * C + tileN + wc];
        *(float4*)&Ws[wr][wc] = wv;
        __syncthreads();

        #pragma unroll
        for (int kk = 0; kk < 16; kk++) {
            float4 bv = *(const float4*)&Ws[kk][tx * 4];
            #pragma unroll
            for (int i = 0; i < 4; i++) {
                float a = Xs[ty * 4 + i][kk];
                acc[i][0] = fmaf(a, bv.x, acc[i][0]);
                acc[i][1] = fmaf(a, bv.y, acc[i][1]);
                acc[i][2] = fmaf(a, bv.z, acc[i][2]);
                acc[i][3] = fmaf(a, bv.w, acc[i][3]);
            }
        }
        __syncthreads();
    }

    const int n0 = tileN + tx * 4;
    const float b0 = bias[n0 + 0];
    const float b1 = bias[n0 + 1];
    const float b2 = bias[n0 + 2];
    const float b3 = bias[n0 + 3];

    #pragma unroll
    for (int i = 0; i < 4; i++) {
        const int mrow = tileM + ty * 4 + i;
        float v0 = acc[i][0] + b0;
        float v1 = acc[i][1] + b1;
        float v2 = acc[i][2] + b2;
        float v3 = acc[i][3] + b3;

        if (WHICH == 3) {
            float4 o4 = make_float4(v0, v1, v2, v3);
            *(float4*)&out[(size_t)mrow * C + n0] = o4;
        } else {
            const int bb = mrow / T;
            const int tt = mrow % T;
            const int h  = n0 / HS;
            const int d0 = n0 % HS;
            if (WHICH < 2) {
                // RoPE on pairs (d0,d0+1), (d0+2,d0+3)
                {
                    const int ip = d0 >> 1;
                    const float inv = powf(10000.0f, -(float)ip / 32.0f);
                    const float ang = (float)tt * inv;
                    float sn, cs; sincosf(ang, &sn, &cs);
                    float r0 = v0 * cs - v1 * sn;
                    float r1 = v0 * sn + v1 * cs;
                    v0 = r0; v1 = r1;
                }
                {
                    const int ip = (d0 + 2) >> 1;
                    const float inv = powf(10000.0f, -(float)ip / 32.0f);
                    const float ang = (float)tt * inv;
                    float sn, cs; sincosf(ang, &sn, &cs);
                    float r0 = v2 * cs - v3 * sn;
                    float r1 = v2 * sn + v3 * cs;
                    v2 = r0; v3 = r1;
                }
            }
            float* dst = &out[(((size_t)bb * NH + h) * T + tt) * HS + d0];
            float4 o4 = make_float4(v0, v1, v2, v3);
            *(float4*)dst = o4;
        }
    }
}

// ---------------------------------------------------------------------------
// Flash attention, fp32. Block = 128 q rows (1/thread), k/v tiles of 64.
// ---------------------------------------------------------------------------
__global__ __launch_bounds__(128)
void attn_kernel()
{
    __shared__ float Ks[64][64];
    __shared__ float Vs[64][64];

    const int qt  = blockIdx.x;     // q tile (128 rows)
    const int h   = blockIdx.y;
    const int bb  = blockIdx.z;
    const int tid = threadIdx.x;
    const int qi  = qt * 128 + tid;

    const float* qptr = g_q + (((size_t)bb * NH + h) * T + qi) * HS;
    float q[HS];
    #pragma unroll
    for (int d = 0; d < HS; d += 4) {
        float4 v = *(const float4*)&qptr[d];
        q[d] = v.x; q[d+1] = v.y; q[d+2] = v.z; q[d+3] = v.w;
    }

    float o[HS];
    #pragma unroll
    for (int d = 0; d < HS; d++) o[d] = 0.0f;
    float m = -1e30f, l = 0.0f;

    const float* kbase = g_k + (((size_t)bb * NH + h) * T) * HS;
    const float* vbase = g_v + (((size_t)bb * NH + h) * T) * HS;
    const int ktmax = qt * 2 + 1;

    for (int kt = 0; kt <= ktmax; kt++) {
        // cooperative tile load: 64x64 contiguous floats each = 1024 float4
        const float4* ksrc = (const float4*)(kbase + (size_t)kt * 64 * HS);
        const float4* vsrc = (const float4*)(vbase + (size_t)kt * 64 * HS);
        float4* kdst = (float4*)&Ks[0][0];
        float4* vdst = (float4*)&Vs[0][0];
        #pragma unroll
        for (int i = 0; i < 8; i++) {
            kdst[tid + i * 128] = ksrc[tid + i * 128];
            vdst[tid + i * 128] = vsrc[tid + i * 128];
        }
        __syncthreads();

        // two chunks of 32 k-columns to bound register pressure
        #pragma unroll
        for (int ch = 0; ch < 2; ch++) {
            float s[32];
            float smax = m;
            #pragma unroll
            for (int j = 0; j < 32; j++) {
                const int jj = ch * 32 + j;
                float a = 0.0f;
                #pragma unroll
                for (int d = 0; d < HS; d += 4) {
                    float4 kv = *(const float4*)&Ks[jj][d];
                    a = fmaf(q[d+0], kv.x, a);
                    a = fmaf(q[d+1], kv.y, a);
                    a = fmaf(q[d+2], kv.z, a);
                    a = fmaf(q[d+3], kv.w, a);
                }
                a *= 0.125f;                       // 1/sqrt(64)
                const int kidx = kt * 64 + jj;
                if (kidx > qi) a = -1e30f;
                s[j] = a;
                smax = fmaxf(smax, a);
            }
            const float corr = __expf(m - smax);
            m = smax;
            l *= corr;
            #pragma unroll
            for (int d = 0; d < HS; d++) o[d] *= corr;
            #pragma unroll
            for (int j = 0; j < 32; j++) {
                const int jj = ch * 32 + j;
                const float p = __expf(s[j] - m);
                l += p;
                #pragma unroll
                for (int d = 0; d < HS; d += 4) {
                    float4 vv = *(const float4*)&Vs[jj][d];
                    o[d+0] = fmaf(p, vv.x, o[d+0]);
                    o[d+1] = fmaf(p, vv.y, o[d+1]);
                    o[d+2] = fmaf(p, vv.z, o[d+2]);
                    o[d+3] = fmaf(p, vv.w, o[d+3]);
                }
            }
        }
        __syncthreads();
    }

    const float linv = 1.0f / l;
    float* outp = g_att + ((size_t)bb * T + qi) * C + h * HS;
    #pragma unroll
    for (int d = 0; d < HS; d += 4) {
        float4 o4 = make_float4(o[d] * linv, o[d+1] * linv, o[d+2] * linv, o[d+3] * linv);
        *(float4*)&outp[d] = o4;
    }
}

// ---------------------------------------------------------------------------
extern "C" void kernel_launch(void* const* d_in, const int* in_sizes, int n_in,
                              void* d_out, int out_size)
{
    const float* x  = (const float*)d_in[0];
    const float* Wq = (const float*)d_in[1];
    const float* bq = (const float*)d_in[2];
    const float* Wk = (const float*)d_in[3];
    const float* bk = (const float*)d_in[4];
    const float* Wv = (const float*)d_in[5];
    const float* bv = (const float*)d_in[6];
    const float* Wp = (const float*)d_in[7];
    const float* bp = (const float*)d_in[8];
    float* out = (float*)d_out;

    dim3 gg(C / 64, M / 64);   // 16 x 128
    gemm_kernel<0><<<gg, 256>>>(x, Wq, bq, nullptr);
    gemm_kernel<1><<<gg, 256>>>(x, Wk, bk, nullptr);
    gemm_kernel<2><<<gg, 256>>>(x, Wv, bv, nullptr);

    dim3 ga(T / 128, NH, Bz);  // 16 x 16 x 4
    attn_kernel<<<ga, 128>>>();

    gemm_kernel<3><<<gg, 256>>>(nullptr, Wp, bp, out);
}

// round 2
// speedup vs baseline: 1.0528x; 1.0528x over previous
#include <cuda_runtime.h>
#include <math.h>
#include <stdint.h>

#define Bz 4
#define T 2048
#define C 1024
#define NH 16
#define HS 64
#define M (Bz*T)

// Scratch (allocation-free rule: __device__ globals)
__device__ float g_q[Bz*NH*T*HS];   // [B,NH,T,HS]
__device__ float g_k[Bz*NH*T*HS];
__device__ float g_v[Bz*NH*T*HS];
__device__ float g_att[M*C];        // [B,T,C]

// ---------------------------------------------------------------------------
// helpers
// ---------------------------------------------------------------------------
__device__ __forceinline__ float f2tf32(float f) {
    uint32_t u;
    asm("cvt.rna.tf32.f32 %0, %1;" : "=r"(u) : "f"(f));
    return __uint_as_float(u);
}

__device__ __forceinline__ void mma_tf32(float4 &d,
    uint32_t a0, uint32_t a1, uint32_t a2, uint32_t a3,
    uint32_t b0, uint32_t b1)
{
    asm volatile(
        "mma.sync.aligned.m16n8k8.row.col.f32.tf32.tf32.f32 "
        "{%0,%1,%2,%3}, {%4,%5,%6,%7}, {%8,%9}, {%0,%1,%2,%3};\n"
        : "+f"(d.x), "+f"(d.y), "+f"(d.z), "+f"(d.w)
        : "r"(a0), "r"(a1), "r"(a2), "r"(a3), "r"(b0), "r"(b1));
}

// ---------------------------------------------------------------------------
// Tensor-core GEMM: out = X[M,C] @ W[C,C] + bias
// Block tile 128x128, BK=32, 256 threads (8 warps), warp tile 64x32.
// Packed smem layouts: A fragments = 1x LDS.128, B fragments = 1x LDS.64.
// WHICH: 0 -> g_q (RoPE+heads), 1 -> g_k (RoPE+heads), 2 -> g_v (heads),
//        3 -> X=g_att, out=param (row-major)
// ---------------------------------------------------------------------------
template<int WHICH>
__global__ __launch_bounds__(256)
void gemm_tc(const float* __restrict__ Xin,
             const float* __restrict__ W,
             const float* __restrict__ bias,
             float* __restrict__ outp)
{
    // A: [m16(8)][k8(4)][gid(8)][tig(4)] x float4 {(g,t),(g+8,t),(g,t+4),(g+8,t+4)}
    __shared__ float4 As2[1024];   // 16 KB
    // B: [n8(16)][k8(4)][gid(8)][tig(4)] x float2 {(t,g),(t+4,g)}
    __shared__ float2 Bs2[2048];   // 16 KB

    const float* X = (WHICH == 3) ? g_att : Xin;
    float* out;
    if (WHICH == 0)      out = g_q;
    else if (WHICH == 1) out = g_k;
    else if (WHICH == 2) out = g_v;
    else                 out = outp;

    const int tid   = threadIdx.x;
    const int lane  = tid & 31;
    const int warp  = tid >> 5;
    const int warpM = warp >> 2;     // 0..1
    const int warpN = warp & 3;      // 0..3
    const int gid   = lane >> 2;     // 0..7
    const int tig   = lane & 3;      // 0..3

    const int tileM = blockIdx.y * 128;
    const int tileN = blockIdx.x * 128;

    float4 acc[4][4];
    #pragma unroll
    for (int i = 0; i < 4; i++)
        #pragma unroll
        for (int j = 0; j < 4; j++)
            acc[i][j] = make_float4(0.f, 0.f, 0.f, 0.f);

    float4 ra[4], rb[4];
    // prologue: load first k-tile into regs
    #pragma unroll
    for (int i = 0; i < 4; i++) {
        int idx = tid + i * 256;
        ra[i] = *(const float4*)&X[(size_t)(tileM + (idx >> 3)) * C + ((idx & 7) * 4)];
        rb[i] = *(const float4*)&W[(size_t)(idx >> 5) * C + tileN + (idx & 31) * 4];
    }

    float* Af = (float*)As2;
    float* Bf = (float*)Bs2;

    for (int k0 = 0; k0 < C; k0 += 32) {
        // pack + store current tile (with tf32 conversion)
        #pragma unroll
        for (int i = 0; i < 4; i++) {
            int idx = tid + i * 256;
            {   // A element block: row m, cols c..c+3
                int m = idx >> 3, c = (idx & 7) * 4;
                int m16 = m >> 4, g = m & 7, rh = (m >> 3) & 1;
                int k8 = c >> 3, hf = (c >> 2) & 1;
                int base = (((m16 * 4 + k8) * 32 + g * 4) * 4) + hf * 2 + rh;
                Af[base + 0 ] = f2tf32(ra[i].x);
                Af[base + 4 ] = f2tf32(ra[i].y);
                Af[base + 8 ] = f2tf32(ra[i].z);
                Af[base + 12] = f2tf32(ra[i].w);
            }
            {   // B element block: row k, cols n..n+3
                int k = idx >> 5, n4 = (idx & 31) * 4;
                int k8 = k >> 3, tg = k & 3, hf = (k >> 2) & 1;
                int n8 = n4 >> 3, g0 = n4 & 7;   // 0 or 4
                int base = (((n8 * 4 + k8) * 32 + g0 * 4 + tg) * 2) + hf;
                Bf[base + 0 ] = f2tf32(rb[i].x);
                Bf[base + 8 ] = f2tf32(rb[i].y);
                Bf[base + 16] = f2tf32(rb[i].z);
                Bf[base + 24] = f2tf32(rb[i].w);
            }
        }
        __syncthreads();

        // prefetch next k-tile into regs (overlaps with mma below)
        if (k0 + 32 < C) {
            #pragma unroll
            for (int i = 0; i < 4; i++) {
                int idx = tid + i * 256;
                ra[i] = *(const float4*)&X[(size_t)(tileM + (idx >> 3)) * C + k0 + 32 + ((idx & 7) * 4)];
                rb[i] = *(const float4*)&W[(size_t)(k0 + 32 + (idx >> 5)) * C + tileN + (idx & 31) * 4];
            }
        }

        // compute: 4 k-steps of m16n8k8
        #pragma unroll
        for (int ks = 0; ks < 4; ks++) {
            uint32_t af[4][4];
            uint32_t bfr[4][2];
            #pragma unroll
            for (int mf = 0; mf < 4; mf++) {
                float4 v = As2[((warpM * 4 + mf) * 4 + ks) * 32 + gid * 4 + tig];
                af[mf][0] = __float_as_uint(v.x);
                af[mf][1] = __float_as_uint(v.y);
                af[mf][2] = __float_as_uint(v.z);
                af[mf][3] = __float_as_uint(v.w);
            }
            #pragma unroll
            for (int nf = 0; nf < 4; nf++) {
                float2 v = Bs2[((warpN * 4 + nf) * 4 + ks) * 32 + gid * 4 + tig];
                bfr[nf][0] = __float_as_uint(v.x);
                bfr[nf][1] = __float_as_uint(v.y);
            }
            #pragma unroll
            for (int mf = 0; mf < 4; mf++)
                #pragma unroll
                for (int nf = 0; nf < 4; nf++)
                    mma_tf32(acc[mf][nf],
                             af[mf][0], af[mf][1], af[mf][2], af[mf][3],
                             bfr[nf][0], bfr[nf][1]);
        }
        __syncthreads();
    }

    // epilogue
    #pragma unroll
    for (int nf = 0; nf < 4; nf++) {
        const int n0 = tileN + warpN * 32 + nf * 8 + tig * 2;
        const float b0v = bias[n0];
        const float b1v = bias[n0 + 1];
        float inv = 0.f;
        if (WHICH < 2) {
            const int ip = (n0 & 63) >> 1;
            inv = powf(10000.0f, -(float)ip / 32.0f);
        }
        #pragma unroll
        for (int mf = 0; mf < 4; mf++) {
            float4 a = acc[mf][nf];
            const int r0 = tileM + warpM * 64 + mf * 16 + gid;
            float x0 = a.x + b0v, x1 = a.y + b1v;   // row r0
            float y0 = a.z + b0v, y1 = a.w + b1v;   // row r0+8
            if (WHICH == 3) {
                *(float2*)&out[(size_t)r0 * C + n0]       = make_float2(x0, x1);
                *(float2*)&out[(size_t)(r0 + 8) * C + n0] = make_float2(y0, y1);
            } else {
                const int bb = r0 / T;
                const int t0 = r0 % T;
                const int h  = n0 >> 6;
                const int d0 = n0 & 63;
                if (WHICH < 2) {
                    float sn, cs;
                    sincosf((float)t0 * inv, &sn, &cs);
                    float u0 = x0 * cs - x1 * sn;
                    float u1 = x0 * sn + x1 * cs;
                    x0 = u0; x1 = u1;
                    sincosf((float)(t0 + 8) * inv, &sn, &cs);
                    float w0 = y0 * cs - y1 * sn;
                    float w1 = y0 * sn + y1 * cs;
                    y0 = w0; y1 = w1;
                }
                float* dst = out + (((size_t)bb * NH + h) * T + t0) * HS + d0;
                *(float2*)dst            = make_float2(x0, x1);
                *(float2*)(dst + 8 * HS) = make_float2(y0, y1);
            }
        }
    }
}

// ---------------------------------------------------------------------------
// Flash attention, fp32, ILP-fixed. Block = 128 q rows (1/thread), kv tiles 64.
// ---------------------------------------------------------------------------
__global__ __launch_bounds__(128)
void attn_kernel()
{
    __shared__ float Ks[64][64];
    __shared__ float Vs[64][64];

    const int qt  = gridDim.x - 1 - blockIdx.x;   // big tiles launch first
    const int h   = blockIdx.y;
    const int bb  = blockIdx.z;
    const int tid = threadIdx.x;
    const int qi  = qt * 128 + tid;

    const float* qptr = g_q + (((size_t)bb * NH + h) * T + qi) * HS;
    float q[HS];
    #pragma unroll
    for (int d = 0; d < HS; d += 4) {
        float4 v = *(const float4*)&qptr[d];
        q[d] = v.x; q[d+1] = v.y; q[d+2] = v.z; q[d+3] = v.w;
    }

    float o[HS];
    #pragma unroll
    for (int d = 0; d < HS; d++) o[d] = 0.0f;
    float m = -1e30f, l = 0.0f;

    const float* kbase = g_k + (((size_t)bb * NH + h) * T) * HS;
    const float* vbase = g_v + (((size_t)bb * NH + h) * T) * HS;
    const int ktmax = qt * 2 + 1;

    for (int kt = 0; kt <= ktmax; kt++) {
        const float4* ksrc = (const float4*)(kbase + (size_t)kt * 64 * HS);
        const float4* vsrc = (const float4*)(vbase + (size_t)kt * 64 * HS);
        float4* kdst = (float4*)&Ks[0][0];
        float4* vdst = (float4*)&Vs[0][0];
        #pragma unroll
        for (int i = 0; i < 8; i++) {
            kdst[tid + i * 128] = ksrc[tid + i * 128];
            vdst[tid + i * 128] = vsrc[tid + i * 128];
        }
        __syncthreads();

        const bool needMask = (kt >= qt * 2);

        #pragma unroll
        for (int ch = 0; ch < 2; ch++) {
            float s[32];
            float smax = m;
            #pragma unroll
            for (int j = 0; j < 32; j++) {
                const int jj = ch * 32 + j;
                float a0 = 0.f, a1 = 0.f, a2 = 0.f, a3 = 0.f;
                #pragma unroll
                for (int d = 0; d < HS; d += 16) {
                    float4 k0v = *(const float4*)&Ks[jj][d];
                    float4 k1v = *(const float4*)&Ks[jj][d+4];
                    float4 k2v = *(const float4*)&Ks[jj][d+8];
                    float4 k3v = *(const float4*)&Ks[jj][d+12];
                    a0 = fmaf(q[d+0],  k0v.x, a0);
                    a0 = fmaf(q[d+1],  k0v.y, a0);
                    a0 = fmaf(q[d+2],  k0v.z, a0);
                    a0 = fmaf(q[d+3],  k0v.w, a0);
                    a1 = fmaf(q[d+4],  k1v.x, a1);
                    a1 = fmaf(q[d+5],  k1v.y, a1);
                    a1 = fmaf(q[d+6],  k1v.z, a1);
                    a1 = fmaf(q[d+7],  k1v.w, a1);
                    a2 = fmaf(q[d+8],  k2v.x, a2);
                    a2 = fmaf(q[d+9],  k2v.y, a2);
                    a2 = fmaf(q[d+10], k2v.z, a2);
                    a2 = fmaf(q[d+11], k2v.w, a2);
                    a3 = fmaf(q[d+12], k3v.x, a3);
                    a3 = fmaf(q[d+13], k3v.y, a3);
                    a3 = fmaf(q[d+14], k3v.z, a3);
                    a3 = fmaf(q[d+15], k3v.w, a3);
                }
                float a = ((a0 + a1) + (a2 + a3)) * 0.125f;  // 1/sqrt(64)
                if (needMask) {
                    const int kidx = kt * 64 + jj;
                    if (kidx > qi) a = -1e30f;
                }
                s[j] = a;
                smax = fmaxf(smax, a);
            }
            const float corr = __expf(m - smax);
            m = smax;
            l *= corr;
            #pragma unroll
            for (int d = 0; d < HS; d++) o[d] *= corr;
            #pragma unroll
            for (int j = 0; j < 32; j++) {
                const int jj = ch * 32 + j;
                const float p = __expf(s[j] - m);
                l += p;
                #pragma unroll
                for (int d = 0; d < HS; d += 4) {
                    float4 vv = *(const float4*)&Vs[jj][d];
                    o[d+0] = fmaf(p, vv.x, o[d+0]);
                    o[d+1] = fmaf(p, vv.y, o[d+1]);
                    o[d+2] = fmaf(p, vv.z, o[d+2]);
                    o[d+3] = fmaf(p, vv.w, o[d+3]);
                }
            }
        }
        __syncthreads();
    }

    const float linv = 1.0f / l;
    float* outp = g_att + ((size_t)bb * T + qi) * C + h * HS;
    #pragma unroll
    for (int d = 0; d < HS; d += 4) {
        float4 o4 = make_float4(o[d] * linv, o[d+1] * linv, o[d+2] * linv, o[d+3] * linv);
        *(float4*)&outp[d] = o4;
    }
}

// ---------------------------------------------------------------------------
extern "C" void kernel_launch(void* const* d_in, const int* in_sizes, int n_in,
                              void* d_out, int out_size)
{
    const float* x  = (const float*)d_in[0];
    const float* Wq = (const float*)d_in[1];
    const float* bq = (const float*)d_in[2];
    const float* Wk = (const float*)d_in[3];
    const float* bk = (const float*)d_in[4];
    const float* Wv = (const float*)d_in[5];
    const float* bv = (const float*)d_in[6];
    const float* Wp = (const float*)d_in[7];
    const float* bp = (const float*)d_in[8];
    float* out = (float*)d_out;

    dim3 gg(C / 128, M / 128);   // 8 x 64
    gemm_tc<0><<<gg, 256>>>(x, Wq, bq, nullptr);
    gemm_tc<1><<<gg, 256>>>(x, Wk, bk, nullptr);
    gemm_tc<2><<<gg, 256>>>(x, Wv, bv, nullptr);

    dim3 ga(T / 128, NH, Bz);    // 16 x 16 x 4
    attn_kernel<<<ga, 128>>>();

    gemm_tc<3><<<gg, 256>>>(nullptr, Wp, bp, out);
}

// round 3
// speedup vs baseline: 1.7337x; 1.6468x over previous
#include <cuda_runtime.h>
#include <math.h>
#include <stdint.h>

#define Bz 4
#define T 2048
#define C 1024
#define NH 16
#define HS 64
#define M (Bz*T)

// Scratch (allocation-free rule: __device__ globals)
__device__ float g_q[Bz*NH*T*HS];   // [B,NH,T,HS]
__device__ float g_k[Bz*NH*T*HS];
__device__ float g_v[Bz*NH*T*HS];
__device__ float g_att[M*C];        // [B,T,C]

// ---------------------------------------------------------------------------
// helpers
// ---------------------------------------------------------------------------
__device__ __forceinline__ float f2tf32(float f) {
    uint32_t u;
    asm("cvt.rna.tf32.f32 %0, %1;" : "=r"(u) : "f"(f));
    return __uint_as_float(u);
}

__device__ __forceinline__ void split_tf32(float v, uint32_t &hi, uint32_t &lo) {
    float h = f2tf32(v);
    hi = __float_as_uint(h);
    lo = __float_as_uint(f2tf32(v - h));
}

__device__ __forceinline__ void mma_tf32(float4 &d,
    uint32_t a0, uint32_t a1, uint32_t a2, uint32_t a3,
    uint32_t b0, uint32_t b1)
{
    asm volatile(
        "mma.sync.aligned.m16n8k8.row.col.f32.tf32.tf32.f32 "
        "{%0,%1,%2,%3}, {%4,%5,%6,%7}, {%8,%9}, {%0,%1,%2,%3};\n"
        : "+f"(d.x), "+f"(d.y), "+f"(d.z), "+f"(d.w)
        : "r"(a0), "r"(a1), "r"(a2), "r"(a3), "r"(b0), "r"(b1));
}

// ---------------------------------------------------------------------------
// Tensor-core GEMM: out = X[M,C] @ W[C,C] + bias  (unchanged from round 2)
// ---------------------------------------------------------------------------
template<int WHICH>
__global__ __launch_bounds__(256)
void gemm_tc(const float* __restrict__ Xin,
             const float* __restrict__ W,
             const float* __restrict__ bias,
             float* __restrict__ outp)
{
    __shared__ float4 As2[1024];   // 16 KB
    __shared__ float2 Bs2[2048];   // 16 KB

    const float* X = (WHICH == 3) ? g_att : Xin;
    float* out;
    if (WHICH == 0)      out = g_q;
    else if (WHICH == 1) out = g_k;
    else if (WHICH == 2) out = g_v;
    else                 out = outp;

    const int tid   = threadIdx.x;
    const int lane  = tid & 31;
    const int warp  = tid >> 5;
    const int warpM = warp >> 2;
    const int warpN = warp & 3;
    const int gid   = lane >> 2;
    const int tig   = lane & 3;

    const int tileM = blockIdx.y * 128;
    const int tileN = blockIdx.x * 128;

    float4 acc[4][4];
    #pragma unroll
    for (int i = 0; i < 4; i++)
        #pragma unroll
        for (int j = 0; j < 4; j++)
            acc[i][j] = make_float4(0.f, 0.f, 0.f, 0.f);

    float4 ra[4], rb[4];
    #pragma unroll
    for (int i = 0; i < 4; i++) {
        int idx = tid + i * 256;
        ra[i] = *(const float4*)&X[(size_t)(tileM + (idx >> 3)) * C + ((idx & 7) * 4)];
        rb[i] = *(const float4*)&W[(size_t)(idx >> 5) * C + tileN + (idx & 31) * 4];
    }

    float* Af = (float*)As2;
    float* Bf = (float*)Bs2;

    for (int k0 = 0; k0 < C; k0 += 32) {
        #pragma unroll
        for (int i = 0; i < 4; i++) {
            int idx = tid + i * 256;
            {
                int m = idx >> 3, c = (idx & 7) * 4;
                int m16 = m >> 4, g = m & 7, rh = (m >> 3) & 1;
                int k8 = c >> 3, hf = (c >> 2) & 1;
                int base = (((m16 * 4 + k8) * 32 + g * 4) * 4) + hf * 2 + rh;
                Af[base + 0 ] = f2tf32(ra[i].x);
                Af[base + 4 ] = f2tf32(ra[i].y);
                Af[base + 8 ] = f2tf32(ra[i].z);
                Af[base + 12] = f2tf32(ra[i].w);
            }
            {
                int k = idx >> 5, n4 = (idx & 31) * 4;
                int k8 = k >> 3, tg = k & 3, hf = (k >> 2) & 1;
                int n8 = n4 >> 3, g0 = n4 & 7;
                int base = (((n8 * 4 + k8) * 32 + g0 * 4 + tg) * 2) + hf;
                Bf[base + 0 ] = f2tf32(rb[i].x);
                Bf[base + 8 ] = f2tf32(rb[i].y);
                Bf[base + 16] = f2tf32(rb[i].z);
                Bf[base + 24] = f2tf32(rb[i].w);
            }
        }
        __syncthreads();

        if (k0 + 32 < C) {
            #pragma unroll
            for (int i = 0; i < 4; i++) {
                int idx = tid + i * 256;
                ra[i] = *(const float4*)&X[(size_t)(tileM + (idx >> 3)) * C + k0 + 32 + ((idx & 7) * 4)];
                rb[i] = *(const float4*)&W[(size_t)(k0 + 32 + (idx >> 5)) * C + tileN + (idx & 31) * 4];
            }
        }

        #pragma unroll
        for (int ks = 0; ks < 4; ks++) {
            uint32_t af[4][4];
            uint32_t bfr[4][2];
            #pragma unroll
            for (int mf = 0; mf < 4; mf++) {
                float4 v = As2[((warpM * 4 + mf) * 4 + ks) * 32 + gid * 4 + tig];
                af[mf][0] = __float_as_uint(v.x);
                af[mf][1] = __float_as_uint(v.y);
                af[mf][2] = __float_as_uint(v.z);
                af[mf][3] = __float_as_uint(v.w);
            }
            #pragma unroll
            for (int nf = 0; nf < 4; nf++) {
                float2 v = Bs2[((warpN * 4 + nf) * 4 + ks) * 32 + gid * 4 + tig];
                bfr[nf][0] = __float_as_uint(v.x);
                bfr[nf][1] = __float_as_uint(v.y);
            }
            #pragma unroll
            for (int mf = 0; mf < 4; mf++)
                #pragma unroll
                for (int nf = 0; nf < 4; nf++)
                    mma_tf32(acc[mf][nf],
                             af[mf][0], af[mf][1], af[mf][2], af[mf][3],
                             bfr[nf][0], bfr[nf][1]);
        }
        __syncthreads();
    }

    #pragma unroll
    for (int nf = 0; nf < 4; nf++) {
        const int n0 = tileN + warpN * 32 + nf * 8 + tig * 2;
        const float b0v = bias[n0];
        const float b1v = bias[n0 + 1];
        float inv = 0.f;
        if (WHICH < 2) {
            const int ip = (n0 & 63) >> 1;
            inv = powf(10000.0f, -(float)ip / 32.0f);
        }
        #pragma unroll
        for (int mf = 0; mf < 4; mf++) {
            float4 a = acc[mf][nf];
            const int r0 = tileM + warpM * 64 + mf * 16 + gid;
            float x0 = a.x + b0v, x1 = a.y + b1v;
            float y0 = a.z + b0v, y1 = a.w + b1v;
            if (WHICH == 3) {
                *(float2*)&out[(size_t)r0 * C + n0]       = make_float2(x0, x1);
                *(float2*)&out[(size_t)(r0 + 8) * C + n0] = make_float2(y0, y1);
            } else {
                const int bb = r0 / T;
                const int t0 = r0 % T;
                const int h  = n0 >> 6;
                const int d0 = n0 & 63;
                if (WHICH < 2) {
                    float sn, cs;
                    sincosf((float)t0 * inv, &sn, &cs);
                    float u0 = x0 * cs - x1 * sn;
                    float u1 = x0 * sn + x1 * cs;
                    x0 = u0; x1 = u1;
                    sincosf((float)(t0 + 8) * inv, &sn, &cs);
                    float w0 = y0 * cs - y1 * sn;
                    float w1 = y0 * sn + y1 * cs;
                    y0 = w0; y1 = w1;
                }
                float* dst = out + (((size_t)bb * NH + h) * T + t0) * HS + d0;
                *(float2*)dst            = make_float2(x0, x1);
                *(float2*)(dst + 8 * HS) = make_float2(y0, y1);
            }
        }
    }
}

// ---------------------------------------------------------------------------
// Tensor-core flash attention (split-tf32, fp32-accurate).
// Block: 64 q rows, 4 warps (16 rows each). K/V tiles of 64 keys.
// Ks [key][68]  -> QK B-fragments conflict-free.
// Vt [dim][68]  -> PV B-fragments conflict-free.
// P remapped C-frag -> A-frag via 8 shuffles per k-step.
// ---------------------------------------------------------------------------
__global__ __launch_bounds__(128)
void attn_tc()
{
    __shared__ float Ks[64 * 68];
    __shared__ float Vt[64 * 68];

    const int qt   = gridDim.x - 1 - blockIdx.x;   // big tiles first
    const int h    = blockIdx.y;
    const int bb   = blockIdx.z;
    const int tid  = threadIdx.x;
    const int lane = tid & 31;
    const int warp = tid >> 5;
    const int g    = lane >> 2;
    const int t    = lane & 3;

    const float* kbase = g_k + ((size_t)(bb * NH + h) * T) * HS;
    const float* vbase = g_v + ((size_t)(bb * NH + h) * T) * HS;
    const float* qbase = g_q + ((size_t)(bb * NH + h) * T + (size_t)qt * 64) * HS;

    const int rowL = warp * 16 + g;   // local row (0..63), second row +8

    // Q fragments (pre-scaled by 1/sqrt(HS)), split hi/lo. 8 k-steps.
    uint32_t qhi[8][4], qlo[8][4];
    #pragma unroll
    for (int ks = 0; ks < 8; ks++) {
        float a0 = qbase[(size_t)rowL * HS + ks * 8 + t] * 0.125f;
        float a1 = qbase[(size_t)(rowL + 8) * HS + ks * 8 + t] * 0.125f;
        float a2 = qbase[(size_t)rowL * HS + ks * 8 + t + 4] * 0.125f;
        float a3 = qbase[(size_t)(rowL + 8) * HS + ks * 8 + t + 4] * 0.125f;
        split_tf32(a0, qhi[ks][0], qlo[ks][0]);
        split_tf32(a1, qhi[ks][1], qlo[ks][1]);
        split_tf32(a2, qhi[ks][2], qlo[ks][2]);
        split_tf32(a3, qhi[ks][3], qlo[ks][3]);
    }

    float4 O[8];
    #pragma unroll
    for (int i = 0; i < 8; i++) O[i] = make_float4(0.f, 0.f, 0.f, 0.f);
    float m0 = -1e30f, m1 = -1e30f, l0 = 0.f, l1 = 0.f;

    for (int kt = 0; kt <= qt; kt++) {
        // --- load K tile [key][dim] -> Ks[key*68+dim] (float4 stores) ---
        #pragma unroll
        for (int i = 0; i < 8; i++) {
            int idx = tid + i * 128;
            int key = idx >> 4;
            int d0  = (idx & 15) * 4;
            float4 kv = *(const float4*)&kbase[(size_t)(kt * 64 + key) * HS + d0];
            *(float4*)&Ks[key * 68 + d0] = kv;
        }
        // --- load V tile transposed -> Vt[dim*68+key] (conflict-free STS) ---
        #pragma unroll
        for (int i = 0; i < 8; i++) {
            int idx = tid + i * 128;
            int key = idx & 63;
            int d0  = (idx >> 6) * 4;
            float4 vv = *(const float4*)&vbase[(size_t)(kt * 64 + key) * HS + d0];
            Vt[(d0 + 0) * 68 + key] = vv.x;
            Vt[(d0 + 1) * 68 + key] = vv.y;
            Vt[(d0 + 2) * 68 + key] = vv.z;
            Vt[(d0 + 3) * 68 + key] = vv.w;
        }
        __syncthreads();

        // --- scores S = Q Kt (3-term split-tf32) ---
        float4 S[8];
        #pragma unroll
        for (int i = 0; i < 8; i++) S[i] = make_float4(0.f, 0.f, 0.f, 0.f);

        #pragma unroll
        for (int ks = 0; ks < 8; ks++) {
            #pragma unroll
            for (int n8 = 0; n8 < 8; n8++) {
                float b0f = Ks[(n8 * 8 + g) * 68 + ks * 8 + t];
                float b1f = Ks[(n8 * 8 + g) * 68 + ks * 8 + t + 4];
                uint32_t bh0, bl0, bh1, bl1;
                split_tf32(b0f, bh0, bl0);
                split_tf32(b1f, bh1, bl1);
                mma_tf32(S[n8], qhi[ks][0], qhi[ks][1], qhi[ks][2], qhi[ks][3], bh0, bh1);
                mma_tf32(S[n8], qhi[ks][0], qhi[ks][1], qhi[ks][2], qhi[ks][3], bl0, bl1);
                mma_tf32(S[n8], qlo[ks][0], qlo[ks][1], qlo[ks][2], qlo[ks][3], bh0, bh1);
            }
        }

        // --- causal mask on diagonal tile ---
        if (kt == qt) {
            #pragma unroll
            for (int n8 = 0; n8 < 8; n8++) {
                int c0 = n8 * 8 + 2 * t;
                if (c0     > rowL    ) S[n8].x = -1e30f;
                if (c0 + 1 > rowL    ) S[n8].y = -1e30f;
                if (c0     > rowL + 8) S[n8].z = -1e30f;
                if (c0 + 1 > rowL + 8) S[n8].w = -1e30f;
            }
        }

        // --- online softmax ---
        float mx0 = -1e30f, mx1 = -1e30f;
        #pragma unroll
        for (int n8 = 0; n8 < 8; n8++) {
            mx0 = fmaxf(mx0, fmaxf(S[n8].x, S[n8].y));
            mx1 = fmaxf(mx1, fmaxf(S[n8].z, S[n8].w));
        }
        mx0 = fmaxf(mx0, __shfl_xor_sync(0xffffffffu, mx0, 1));
        mx0 = fmaxf(mx0, __shfl_xor_sync(0xffffffffu, mx0, 2));
        mx1 = fmaxf(mx1, __shfl_xor_sync(0xffffffffu, mx1, 1));
        mx1 = fmaxf(mx1, __shfl_xor_sync(0xffffffffu, mx1, 2));

        float nm0 = fmaxf(m0, mx0);
        float nm1 = fmaxf(m1, mx1);
        float c0 = __expf(m0 - nm0);
        float c1 = __expf(m1 - nm1);
        m0 = nm0; m1 = nm1;
        l0 *= c0;  l1 *= c1;

        #pragma unroll
        for (int n8 = 0; n8 < 8; n8++) {
            S[n8].x = __expf(S[n8].x - nm0);
            S[n8].y = __expf(S[n8].y - nm0);
            S[n8].z = __expf(S[n8].z - nm1);
            S[n8].w = __expf(S[n8].w - nm1);
            l0 += S[n8].x + S[n8].y;
            l1 += S[n8].z + S[n8].w;
            O[n8].x *= c0; O[n8].y *= c0;
            O[n8].z *= c1; O[n8].w *= c1;
        }

        // --- O += P V (3-term split-tf32) ---
        const int slBase = (lane & ~3) | (t >> 1);
        #pragma unroll
        for (int ks = 0; ks < 8; ks++) {
            // remap C-frag (p) -> A-frag via shuffles
            float x0 = __shfl_sync(0xffffffffu, S[ks].x, slBase);
            float y0 = __shfl_sync(0xffffffffu, S[ks].y, slBase);
            float z0 = __shfl_sync(0xffffffffu, S[ks].z, slBase);
            float w0 = __shfl_sync(0xffffffffu, S[ks].w, slBase);
            float x1 = __shfl_sync(0xffffffffu, S[ks].x, slBase + 2);
            float y1 = __shfl_sync(0xffffffffu, S[ks].y, slBase + 2);
            float z1 = __shfl_sync(0xffffffffu, S[ks].z, slBase + 2);
            float w1 = __shfl_sync(0xffffffffu, S[ks].w, slBase + 2);
            float a0 = (t & 1) ? y0 : x0;
            float a1 = (t & 1) ? w0 : z0;
            float a2 = (t & 1) ? y1 : x1;
            float a3 = (t & 1) ? w1 : z1;
            uint32_t ah[4], al[4];
            split_tf32(a0, ah[0], al[0]);
            split_tf32(a1, ah[1], al[1]);
            split_tf32(a2, ah[2], al[2]);
            split_tf32(a3, ah[3], al[3]);

            #pragma unroll
            for (int n8 = 0; n8 < 8; n8++) {
                float b0f = Vt[(n8 * 8 + g) * 68 + ks * 8 + t];
                float b1f = Vt[(n8 * 8 + g) * 68 + ks * 8 + t + 4];
                uint32_t bh0, bl0, bh1, bl1;
                split_tf32(b0f, bh0, bl0);
                split_tf32(b1f, bh1, bl1);
                mma_tf32(O[n8], ah[0], ah[1], ah[2], ah[3], bh0, bh1);
                mma_tf32(O[n8], ah[0], ah[1], ah[2], ah[3], bl0, bl1);
                mma_tf32(O[n8], al[0], al[1], al[2], al[3], bh0, bh1);
            }
        }
        __syncthreads();
    }

    // final row-sum reduce + normalize + store
    l0 += __shfl_xor_sync(0xffffffffu, l0, 1);
    l0 += __shfl_xor_sync(0xffffffffu, l0, 2);
    l1 += __shfl_xor_sync(0xffffffffu, l1, 1);
    l1 += __shfl_xor_sync(0xffffffffu, l1, 2);
    const float i0 = 1.0f / l0;
    const float i1 = 1.0f / l1;

    float* ob = g_att + ((size_t)bb * T + (size_t)qt * 64 + rowL) * C + h * 64;
    #pragma unroll
    for (int n8 = 0; n8 < 8; n8++) {
        *(float2*)&ob[n8 * 8 + 2 * t]           = make_float2(O[n8].x * i0, O[n8].y * i0);
        *(float2*)&ob[8 * C + n8 * 8 + 2 * t]   = make_float2(O[n8].z * i1, O[n8].w * i1);
    }
}

// ---------------------------------------------------------------------------
extern "C" void kernel_launch(void* const* d_in, const int* in_sizes, int n_in,
                              void* d_out, int out_size)
{
    const float* x  = (const float*)d_in[0];
    const float* Wq = (const float*)d_in[1];
    const float* bq = (const float*)d_in[2];
    const float* Wk = (const float*)d_in[3];
    const float* bk = (const float*)d_in[4];
    const float* Wv = (const float*)d_in[5];
    const float* bv = (const float*)d_in[6];
    const float* Wp = (const float*)d_in[7];
    const float* bp = (const float*)d_in[8];
    float* out = (float*)d_out;

    dim3 gg(C / 128, M / 128);   // 8 x 64
    gemm_tc<0><<<gg, 256>>>(x, Wq, bq, nullptr);
    gemm_tc<1><<<gg, 256>>>(x, Wk, bk, nullptr);
    gemm_tc<2><<<gg, 256>>>(x, Wv, bv, nullptr);

    dim3 ga(T / 64, NH, Bz);     // 32 x 16 x 4
    attn_tc<<<ga, 128>>>();

    gemm_tc<3><<<gg, 256>>>(nullptr, Wp, bp, out);
}

// round 4
// speedup vs baseline: 2.1109x; 1.2175x over previous
#include <cuda_runtime.h>
#include <math.h>
#include <stdint.h>

#define Bz 4
#define T 2048
#define C 1024
#define NH 16
#define HS 64
#define M (Bz*T)

// Scratch (allocation-free rule: __device__ globals)
__device__ float g_q[Bz*NH*T*HS];   // [B,NH,T,HS]
__device__ float g_k[Bz*NH*T*HS];
__device__ float g_v[Bz*NH*T*HS];
__device__ float g_att[M*C];        // [B,T,C]

// ---------------------------------------------------------------------------
// helpers
// ---------------------------------------------------------------------------
__device__ __forceinline__ float f2tf32(float f) {
    uint32_t u;
    asm("cvt.rna.tf32.f32 %0, %1;" : "=r"(u) : "f"(f));
    return __uint_as_float(u);
}

__device__ __forceinline__ void split_tf32(float v, uint32_t &hi, uint32_t &lo) {
    float h = f2tf32(v);
    hi = __float_as_uint(h);
    lo = __float_as_uint(f2tf32(v - h));
}

__device__ __forceinline__ void mma_tf32(float4 &d,
    uint32_t a0, uint32_t a1, uint32_t a2, uint32_t a3,
    uint32_t b0, uint32_t b1)
{
    asm volatile(
        "mma.sync.aligned.m16n8k8.row.col.f32.tf32.tf32.f32 "
        "{%0,%1,%2,%3}, {%4,%5,%6,%7}, {%8,%9}, {%0,%1,%2,%3};\n"
        : "+f"(d.x), "+f"(d.y), "+f"(d.z), "+f"(d.w)
        : "r"(a0), "r"(a1), "r"(a2), "r"(a3), "r"(b0), "r"(b1));
}

// ---------------------------------------------------------------------------
// Tensor-core GEMM, double-buffered smem.
// QKV=1: fused Q/K/V projections (grid.x = 24: 3 mats x 8 n-tiles),
//        epilogue = bias + RoPE (Q,K) + head-layout scatter.
// QKV=0: output projection from g_att, plain row-major epilogue.
// Block tile 128x128, BK=32, 256 threads, warp tile 64x32.
// Dynamic smem: [A stage0 | A stage1 | B stage0 | B stage1], 16384 floats.
// ---------------------------------------------------------------------------
template<int QKV>
__global__ __launch_bounds__(256, 2)
void gemm_tc(const float* __restrict__ Xin,
             const float* __restrict__ W0,
             const float* __restrict__ W1,
             const float* __restrict__ W2,
             const float* __restrict__ b0p,
             const float* __restrict__ b1p,
             const float* __restrict__ b2p,
             float* __restrict__ outp)
{
    extern __shared__ float smp[];
    // A per-stage: 4096 floats; B per-stage: 4096 floats
    float* Abase = smp;          // stages at +0, +4096
    float* Bbase = smp + 8192;   // stages at +0, +4096

    const float* X;
    const float* W;
    const float* bias;
    float* out;
    int sel, tileN;
    if (QKV) {
        X = Xin;
        sel = blockIdx.x >> 3;
        tileN = (blockIdx.x & 7) * 128;
        W    = (sel == 0) ? W0 : (sel == 1) ? W1 : W2;
        bias = (sel == 0) ? b0p : (sel == 1) ? b1p : b2p;
        out  = (sel == 0) ? g_q : (sel == 1) ? g_k : g_v;
    } else {
        X = g_att;
        sel = 3;
        tileN = blockIdx.x * 128;
        W = W0; bias = b0p; out = outp;
    }

    const int tid   = threadIdx.x;
    const int lane  = tid & 31;
    const int warp  = tid >> 5;
    const int warpM = warp >> 2;
    const int warpN = warp & 3;
    const int gid   = lane >> 2;
    const int tig   = lane & 3;

    const int tileM = blockIdx.y * 128;

    float4 acc[4][4];
    #pragma unroll
    for (int i = 0; i < 4; i++)
        #pragma unroll
        for (int j = 0; j < 4; j++)
            acc[i][j] = make_float4(0.f, 0.f, 0.f, 0.f);

    float4 ra[4], rb[4];
    #pragma unroll
    for (int i = 0; i < 4; i++) {
        int idx = tid + i * 256;
        ra[i] = *(const float4*)&X[(size_t)(tileM + (idx >> 3)) * C + ((idx & 7) * 4)];
        rb[i] = *(const float4*)&W[(size_t)(idx >> 5) * C + tileN + (idx & 31) * 4];
    }

    // pack a register tile into stage s
    auto pack = [&](int s) {
        float* Af = Abase + s * 4096;
        float* Bf = Bbase + s * 4096;
        #pragma unroll
        for (int i = 0; i < 4; i++) {
            int idx = tid + i * 256;
            {
                int m = idx >> 3, c = (idx & 7) * 4;
                int m16 = m >> 4, g = m & 7, rh = (m >> 3) & 1;
                int k8 = c >> 3, hf = (c >> 2) & 1;
                int base = (((m16 * 4 + k8) * 32 + g * 4) * 4) + hf * 2 + rh;
                Af[base + 0 ] = f2tf32(ra[i].x);
                Af[base + 4 ] = f2tf32(ra[i].y);
                Af[base + 8 ] = f2tf32(ra[i].z);
                Af[base + 12] = f2tf32(ra[i].w);
            }
            {
                int k = idx >> 5, n4 = (idx & 31) * 4;
                int k8 = k >> 3, tg = k & 3, hf = (k >> 2) & 1;
                int n8 = n4 >> 3, g0 = n4 & 7;
                int base = (((n8 * 4 + k8) * 32 + g0 * 4 + tg) * 2) + hf;
                Bf[base + 0 ] = f2tf32(rb[i].x);
                Bf[base + 8 ] = f2tf32(rb[i].y);
                Bf[base + 16] = f2tf32(rb[i].z);
                Bf[base + 24] = f2tf32(rb[i].w);
            }
        }
    };

    pack(0);
    __syncthreads();

    for (int k0 = 0; k0 < C; k0 += 32) {
        const int stage = (k0 >> 5) & 1;
        const bool more = (k0 + 32 < C);

        if (more) {
            #pragma unroll
            for (int i = 0; i < 4; i++) {
                int idx = tid + i * 256;
                ra[i] = *(const float4*)&X[(size_t)(tileM + (idx >> 3)) * C + k0 + 32 + ((idx & 7) * 4)];
                rb[i] = *(const float4*)&W[(size_t)(k0 + 32 + (idx >> 5)) * C + tileN + (idx & 31) * 4];
            }
        }

        const float4* As2 = (const float4*)(Abase + stage * 4096);
        const float2* Bs2 = (const float2*)(Bbase + stage * 4096);
        #pragma unroll
        for (int ks = 0; ks < 4; ks++) {
            uint32_t af[4][4];
            uint32_t bfr[4][2];
            #pragma unroll
            for (int mf = 0; mf < 4; mf++) {
                float4 v = As2[((warpM * 4 + mf) * 4 + ks) * 32 + gid * 4 + tig];
                af[mf][0] = __float_as_uint(v.x);
                af[mf][1] = __float_as_uint(v.y);
                af[mf][2] = __float_as_uint(v.z);
                af[mf][3] = __float_as_uint(v.w);
            }
            #pragma unroll
            for (int nf = 0; nf < 4; nf++) {
                float2 v = Bs2[((warpN * 4 + nf) * 4 + ks) * 32 + gid * 4 + tig];
                bfr[nf][0] = __float_as_uint(v.x);
                bfr[nf][1] = __float_as_uint(v.y);
            }
            #pragma unroll
            for (int mf = 0; mf < 4; mf++)
                #pragma unroll
                for (int nf = 0; nf < 4; nf++)
                    mma_tf32(acc[mf][nf],
                             af[mf][0], af[mf][1], af[mf][2], af[mf][3],
                             bfr[nf][0], bfr[nf][1]);
        }

        if (more) pack(1 - stage);
        __syncthreads();
    }

    // epilogue
    #pragma unroll
    for (int nf = 0; nf < 4; nf++) {
        const int n0 = tileN + warpN * 32 + nf * 8 + tig * 2;
        const float bv0 = bias[n0];
        const float bv1 = bias[n0 + 1];
        float inv = 0.f;
        if (QKV) {
            const int ip = (n0 & 63) >> 1;
            inv = powf(10000.0f, -(float)ip / 32.0f);
        }
        #pragma unroll
        for (int mf = 0; mf < 4; mf++) {
            float4 a = acc[mf][nf];
            const int r0 = tileM + warpM * 64 + mf * 16 + gid;
            float x0 = a.x + bv0, x1 = a.y + bv1;
            float y0 = a.z + bv0, y1 = a.w + bv1;
            if (!QKV) {
                *(float2*)&out[(size_t)r0 * C + n0]       = make_float2(x0, x1);
                *(float2*)&out[(size_t)(r0 + 8) * C + n0] = make_float2(y0, y1);
            } else {
                const int bb = r0 / T;
                const int t0 = r0 % T;
                const int h  = n0 >> 6;
                const int d0 = n0 & 63;
                if (sel < 2) {
                    float sn, cs;
                    sincosf((float)t0 * inv, &sn, &cs);
                    float u0 = x0 * cs - x1 * sn;
                    float u1 = x0 * sn + x1 * cs;
                    x0 = u0; x1 = u1;
                    sincosf((float)(t0 + 8) * inv, &sn, &cs);
                    float w0 = y0 * cs - y1 * sn;
                    float w1 = y0 * sn + y1 * cs;
                    y0 = w0; y1 = w1;
                }
                float* dst = out + (((size_t)bb * NH + h) * T + t0) * HS + d0;
                *(float2*)dst            = make_float2(x0, x1);
                *(float2*)(dst + 8 * HS) = make_float2(y0, y1);
            }
        }
    }
}

// ---------------------------------------------------------------------------
// Tensor-core flash attention.
// QK: 3-term split-tf32 (Q split in regs, K pre-split hi/lo in smem).
// PV: plain tf32 (P cvt on the fly, V pre-converted transposed in smem).
// Block: 64 q rows, 4 warps. Dynamic smem planes: Khi, Klo, Vt (64x68 each).
// ---------------------------------------------------------------------------
__global__ __launch_bounds__(128, 2)
void attn_tc()
{
    extern __shared__ float smp[];
    float* Khi = smp;            // 64*68
    float* Klo = smp + 4352;     // 64*68
    float* Vt  = smp + 8704;     // 64*68 (transposed: [dim][key])

    const int qt   = gridDim.x - 1 - blockIdx.x;   // big tiles first
    const int h    = blockIdx.y;
    const int bb   = blockIdx.z;
    const int tid  = threadIdx.x;
    const int lane = tid & 31;
    const int warp = tid >> 5;
    const int g    = lane >> 2;
    const int t    = lane & 3;

    const float* kbase = g_k + ((size_t)(bb * NH + h) * T) * HS;
    const float* vbase = g_v + ((size_t)(bb * NH + h) * T) * HS;
    const float* qbase = g_q + ((size_t)(bb * NH + h) * T + (size_t)qt * 64) * HS;

    const int rowL = warp * 16 + g;

    uint32_t qhi[8][4], qlo[8][4];
    #pragma unroll
    for (int ks = 0; ks < 8; ks++) {
        float a0 = qbase[(size_t)rowL * HS + ks * 8 + t] * 0.125f;
        float a1 = qbase[(size_t)(rowL + 8) * HS + ks * 8 + t] * 0.125f;
        float a2 = qbase[(size_t)rowL * HS + ks * 8 + t + 4] * 0.125f;
        float a3 = qbase[(size_t)(rowL + 8) * HS + ks * 8 + t + 4] * 0.125f;
        split_tf32(a0, qhi[ks][0], qlo[ks][0]);
        split_tf32(a1, qhi[ks][1], qlo[ks][1]);
        split_tf32(a2, qhi[ks][2], qlo[ks][2]);
        split_tf32(a3, qhi[ks][3], qlo[ks][3]);
    }

    float4 O[8];
    #pragma unroll
    for (int i = 0; i < 8; i++) O[i] = make_float4(0.f, 0.f, 0.f, 0.f);
    float m0 = -1e30f, m1 = -1e30f, l0 = 0.f, l1 = 0.f;

    for (int kt = 0; kt <= qt; kt++) {
        // --- K tile: load, split hi/lo, store [key][68] ---
        #pragma unroll
        for (int i = 0; i < 8; i++) {
            int idx = tid + i * 128;
            int key = idx >> 4;
            int d0  = (idx & 15) * 4;
            float4 kv = *(const float4*)&kbase[(size_t)(kt * 64 + key) * HS + d0];
            float hx = f2tf32(kv.x), hy = f2tf32(kv.y), hz = f2tf32(kv.z), hw = f2tf32(kv.w);
            *(float4*)&Khi[key * 68 + d0] = make_float4(hx, hy, hz, hw);
            *(float4*)&Klo[key * 68 + d0] = make_float4(
                f2tf32(kv.x - hx), f2tf32(kv.y - hy), f2tf32(kv.z - hz), f2tf32(kv.w - hw));
        }
        // --- V tile: load, cvt, store transposed [dim][68] ---
        #pragma unroll
        for (int i = 0; i < 8; i++) {
            int idx = tid + i * 128;
            int key = idx & 63;
            int d0  = (idx >> 6) * 4;
            float4 vv = *(const float4*)&vbase[(size_t)(kt * 64 + key) * HS + d0];
            Vt[(d0 + 0) * 68 + key] = f2tf32(vv.x);
            Vt[(d0 + 1) * 68 + key] = f2tf32(vv.y);
            Vt[(d0 + 2) * 68 + key] = f2tf32(vv.z);
            Vt[(d0 + 3) * 68 + key] = f2tf32(vv.w);
        }
        __syncthreads();

        // --- scores S = Q Kt ---
        float4 S[8];
        #pragma unroll
        for (int i = 0; i < 8; i++) S[i] = make_float4(0.f, 0.f, 0.f, 0.f);

        #pragma unroll
        for (int ks = 0; ks < 8; ks++) {
            #pragma unroll
            for (int n8 = 0; n8 < 8; n8++) {
                const int off = (n8 * 8 + g) * 68 + ks * 8 + t;
                uint32_t bh0 = __float_as_uint(Khi[off]);
                uint32_t bh1 = __float_as_uint(Khi[off + 4]);
                uint32_t bl0 = __float_as_uint(Klo[off]);
                uint32_t bl1 = __float_as_uint(Klo[off + 4]);
                mma_tf32(S[n8], qhi[ks][0], qhi[ks][1], qhi[ks][2], qhi[ks][3], bh0, bh1);
                mma_tf32(S[n8], qhi[ks][0], qhi[ks][1], qhi[ks][2], qhi[ks][3], bl0, bl1);
                mma_tf32(S[n8], qlo[ks][0], qlo[ks][1], qlo[ks][2], qlo[ks][3], bh0, bh1);
            }
        }

        // --- causal mask on diagonal tile ---
        if (kt == qt) {
            #pragma unroll
            for (int n8 = 0; n8 < 8; n8++) {
                int c0 = n8 * 8 + 2 * t;
                if (c0     > rowL    ) S[n8].x = -1e30f;
                if (c0 + 1 > rowL    ) S[n8].y = -1e30f;
                if (c0     > rowL + 8) S[n8].z = -1e30f;
                if (c0 + 1 > rowL + 8) S[n8].w = -1e30f;
            }
        }

        // --- online softmax ---
        float mx0 = -1e30f, mx1 = -1e30f;
        #pragma unroll
        for (int n8 = 0; n8 < 8; n8++) {
            mx0 = fmaxf(mx0, fmaxf(S[n8].x, S[n8].y));
            mx1 = fmaxf(mx1, fmaxf(S[n8].z, S[n8].w));
        }
        mx0 = fmaxf(mx0, __shfl_xor_sync(0xffffffffu, mx0, 1));
        mx0 = fmaxf(mx0, __shfl_xor_sync(0xffffffffu, mx0, 2));
        mx1 = fmaxf(mx1, __shfl_xor_sync(0xffffffffu, mx1, 1));
        mx1 = fmaxf(mx1, __shfl_xor_sync(0xffffffffu, mx1, 2));

        float nm0 = fmaxf(m0, mx0);
        float nm1 = fmaxf(m1, mx1);
        float c0 = __expf(m0 - nm0);
        float c1 = __expf(m1 - nm1);
        m0 = nm0; m1 = nm1;
        l0 *= c0;  l1 *= c1;

        #pragma unroll
        for (int n8 = 0; n8 < 8; n8++) {
            S[n8].x = __expf(S[n8].x - nm0);
            S[n8].y = __expf(S[n8].y - nm0);
            S[n8].z = __expf(S[n8].z - nm1);
            S[n8].w = __expf(S[n8].w - nm1);
            l0 += S[n8].x + S[n8].y;
            l1 += S[n8].z + S[n8].w;
            O[n8].x *= c0; O[n8].y *= c0;
            O[n8].z *= c1; O[n8].w *= c1;
        }

        // --- O += P V (P plain tf32, V pre-converted) ---
        const int slBase = (lane & ~3) | (t >> 1);
        #pragma unroll
        for (int ks = 0; ks < 8; ks++) {
            float x0 = __shfl_sync(0xffffffffu, S[ks].x, slBase);
            float y0 = __shfl_sync(0xffffffffu, S[ks].y, slBase);
            float z0 = __shfl_sync(0xffffffffu, S[ks].z, slBase);
            float w0 = __shfl_sync(0xffffffffu, S[ks].w, slBase);
            float x1 = __shfl_sync(0xffffffffu, S[ks].x, slBase + 2);
            float y1 = __shfl_sync(0xffffffffu, S[ks].y, slBase + 2);
            float z1 = __shfl_sync(0xffffffffu, S[ks].z, slBase + 2);
            float w1 = __shfl_sync(0xffffffffu, S[ks].w, slBase + 2);
            uint32_t a0 = __float_as_uint(f2tf32((t & 1) ? y0 : x0));
            uint32_t a1 = __float_as_uint(f2tf32((t & 1) ? w0 : z0));
            uint32_t a2 = __float_as_uint(f2tf32((t & 1) ? y1 : x1));
            uint32_t a3 = __float_as_uint(f2tf32((t & 1) ? w1 : z1));

            #pragma unroll
            for (int n8 = 0; n8 < 8; n8++) {
                const int off = (n8 * 8 + g) * 68 + ks * 8 + t;
                uint32_t b0 = __float_as_uint(Vt[off]);
                uint32_t b1 = __float_as_uint(Vt[off + 4]);
                mma_tf32(O[n8], a0, a1, a2, a3, b0, b1);
            }
        }
        __syncthreads();
    }

    l0 += __shfl_xor_sync(0xffffffffu, l0, 1);
    l0 += __shfl_xor_sync(0xffffffffu, l0, 2);
    l1 += __shfl_xor_sync(0xffffffffu, l1, 1);
    l1 += __shfl_xor_sync(0xffffffffu, l1, 2);
    const float i0 = 1.0f / l0;
    const float i1 = 1.0f / l1;

    float* ob = g_att + ((size_t)bb * T + (size_t)qt * 64 + rowL) * C + h * 64;
    #pragma unroll
    for (int n8 = 0; n8 < 8; n8++) {
        *(float2*)&ob[n8 * 8 + 2 * t]         = make_float2(O[n8].x * i0, O[n8].y * i0);
        *(float2*)&ob[8 * C + n8 * 8 + 2 * t] = make_float2(O[n8].z * i1, O[n8].w * i1);
    }
}

// ---------------------------------------------------------------------------
extern "C" void kernel_launch(void* const* d_in, const int* in_sizes, int n_in,
                              void* d_out, int out_size)
{
    const float* x  = (const float*)d_in[0];
    const float* Wq = (const float*)d_in[1];
    const float* bq = (const float*)d_in[2];
    const float* Wk = (const float*)d_in[3];
    const float* bk = (const float*)d_in[4];
    const float* Wv = (const float*)d_in[5];
    const float* bv = (const float*)d_in[6];
    const float* Wp = (const float*)d_in[7];
    const float* bp = (const float*)d_in[8];
    float* out = (float*)d_out;

    const int GEMM_SMEM = 16384 * sizeof(float);   // 64 KB
    const int ATTN_SMEM = 3 * 64 * 68 * sizeof(float);   // 52224 B

    cudaFuncSetAttribute(gemm_tc<1>, cudaFuncAttributeMaxDynamicSharedMemorySize, GEMM_SMEM);
    cudaFuncSetAttribute(gemm_tc<0>, cudaFuncAttributeMaxDynamicSharedMemorySize, GEMM_SMEM);
    cudaFuncSetAttribute(attn_tc,    cudaFuncAttributeMaxDynamicSharedMemorySize, ATTN_SMEM);

    dim3 gq(24, M / 128);   // fused QKV: 24 x 64
    gemm_tc<1><<<gq, 256, GEMM_SMEM>>>(x, Wq, Wk, Wv, bq, bk, bv, nullptr);

    dim3 ga(T / 64, NH, Bz);   // 32 x 16 x 4
    attn_tc<<<ga, 128, ATTN_SMEM>>>();

    dim3 gp(8, M / 128);    // 8 x 64
    gemm_tc<0><<<gp, 256, GEMM_SMEM>>>(nullptr, Wp, nullptr, nullptr, bp, nullptr, nullptr, out);
}

// round 5
// speedup vs baseline: 4.3198x; 2.0465x over previous
#include <cuda_runtime.h>
#include <math.h>
#include <stdint.h>

#define Bz 4
#define T 2048
#define C 1024
#define NH 16
#define HS 64
#define M (Bz*T)

// A plane: 128 rows x stride 36 = 4608 floats
// B plane: 32 rows  x stride 136 = 4352 floats
#define ASTRIDE 36
#define BSTRIDE 136
#define STAGE_FLOATS (4608 + 4352)   // 8960

// Scratch (allocation-free rule: __device__ globals)
__device__ float g_q[Bz*NH*T*HS];   // [B,NH,T,HS]
__device__ float g_k[Bz*NH*T*HS];
__device__ float g_v[Bz*NH*T*HS];
__device__ float g_att[M*C];        // [B,T,C]

// ---------------------------------------------------------------------------
// helpers
// ---------------------------------------------------------------------------
__device__ __forceinline__ float f2tf32(float f) {
    uint32_t u;
    asm("cvt.rna.tf32.f32 %0, %1;" : "=r"(u) : "f"(f));
    return __uint_as_float(u);
}

__device__ __forceinline__ void split_tf32(float v, uint32_t &hi, uint32_t &lo) {
    float h = f2tf32(v);
    hi = __float_as_uint(h);
    lo = __float_as_uint(f2tf32(v - h));
}

__device__ __forceinline__ void mma_tf32(float4 &d,
    uint32_t a0, uint32_t a1, uint32_t a2, uint32_t a3,
    uint32_t b0, uint32_t b1)
{
    asm volatile(
        "mma.sync.aligned.m16n8k8.row.col.f32.tf32.tf32.f32 "
        "{%0,%1,%2,%3}, {%4,%5,%6,%7}, {%8,%9}, {%0,%1,%2,%3};\n"
        : "+f"(d.x), "+f"(d.y), "+f"(d.z), "+f"(d.w)
        : "r"(a0), "r"(a1), "r"(a2), "r"(a3), "r"(b0), "r"(b1));
}

// ---------------------------------------------------------------------------
// Tensor-core GEMM, double-buffered row-major padded smem (conflict-free STS
// and conflict-free scalar-LDS fragment loads).
// QKV=1: fused Q/K/V projections (grid.x = 24: 3 mats x 8 n-tiles),
//        epilogue = bias + RoPE (Q,K) + head-layout scatter.
// QKV=0: output projection from g_att, plain row-major epilogue.
// Block tile 128x128, BK=32, 256 threads, warp tile 64x32.
// ---------------------------------------------------------------------------
template<int QKV>
__global__ __launch_bounds__(256, 2)
void gemm_tc(const float* __restrict__ Xin,
             const float* __restrict__ W0,
             const float* __restrict__ W1,
             const float* __restrict__ W2,
             const float* __restrict__ b0p,
             const float* __restrict__ b1p,
             const float* __restrict__ b2p,
             float* __restrict__ outp)
{
    extern __shared__ float smp[];   // [A0 B0][A1 B1], stage stride STAGE_FLOATS

    const float* X;
    const float* W;
    const float* bias;
    float* out;
    int sel, tileN;
    if (QKV) {
        X = Xin;
        sel = blockIdx.x >> 3;
        tileN = (blockIdx.x & 7) * 128;
        W    = (sel == 0) ? W0 : (sel == 1) ? W1 : W2;
        bias = (sel == 0) ? b0p : (sel == 1) ? b1p : b2p;
        out  = (sel == 0) ? g_q : (sel == 1) ? g_k : g_v;
    } else {
        X = g_att;
        sel = 3;
        tileN = blockIdx.x * 128;
        W = W0; bias = b0p; out = outp;
    }

    const int tid   = threadIdx.x;
    const int lane  = tid & 31;
    const int warp  = tid >> 5;
    const int warpM = warp >> 2;     // 0..1
    const int warpN = warp & 3;      // 0..3
    const int g     = lane >> 2;     // 0..7
    const int t     = lane & 3;      // 0..3

    const int tileM = blockIdx.y * 128;

    // GMEM load coords (per i in 0..3, idx = tid + i*256)
    const int am = tid >> 3;          // + 32*i
    const int ac = (tid & 7) * 4;
    const int bk = tid >> 5;          // + 8*i
    const int bc = (tid & 31) * 4;

    float4 acc[4][4];
    #pragma unroll
    for (int i = 0; i < 4; i++)
        #pragma unroll
        for (int j = 0; j < 4; j++)
            acc[i][j] = make_float4(0.f, 0.f, 0.f, 0.f);

    float4 ra[4], rb[4];
    #pragma unroll
    for (int i = 0; i < 4; i++) {
        ra[i] = *(const float4*)&X[(size_t)(tileM + am + 32 * i) * C + ac];
        rb[i] = *(const float4*)&W[(size_t)(bk + 8 * i) * C + tileN + bc];
    }

    auto pack = [&](int s) {
        float* As = smp + s * STAGE_FLOATS;
        float* Bs = As + 4608;
        #pragma unroll
        for (int i = 0; i < 4; i++) {
            float4 av = make_float4(f2tf32(ra[i].x), f2tf32(ra[i].y),
                                    f2tf32(ra[i].z), f2tf32(ra[i].w));
            *(float4*)&As[(am + 32 * i) * ASTRIDE + ac] = av;
            float4 bv = make_float4(f2tf32(rb[i].x), f2tf32(rb[i].y),
                                    f2tf32(rb[i].z), f2tf32(rb[i].w));
            *(float4*)&Bs[(bk + 8 * i) * BSTRIDE + bc] = bv;
        }
    };

    pack(0);
    __syncthreads();

    for (int k0 = 0; k0 < C; k0 += 32) {
        const int stage = (k0 >> 5) & 1;
        const bool more = (k0 + 32 < C);

        if (more) {
            #pragma unroll
            for (int i = 0; i < 4; i++) {
                ra[i] = *(const float4*)&X[(size_t)(tileM + am + 32 * i) * C + k0 + 32 + ac];
                rb[i] = *(const float4*)&W[(size_t)(k0 + 32 + bk + 8 * i) * C + tileN + bc];
            }
        }

        const float* As = smp + stage * STAGE_FLOATS;
        const float* Bs = As + 4608;

        #pragma unroll
        for (int ks = 0; ks < 4; ks++) {
            uint32_t af[4][4];
            uint32_t bfr[4][2];
            #pragma unroll
            for (int mf = 0; mf < 4; mf++) {
                const int r0 = (warpM * 64 + mf * 16 + g) * ASTRIDE + ks * 8 + t;
                af[mf][0] = __float_as_uint(As[r0]);
                af[mf][1] = __float_as_uint(As[r0 + 8 * ASTRIDE]);
                af[mf][2] = __float_as_uint(As[r0 + 4]);
                af[mf][3] = __float_as_uint(As[r0 + 8 * ASTRIDE + 4]);
            }
            #pragma unroll
            for (int nf = 0; nf < 4; nf++) {
                const int c0 = (ks * 8 + t) * BSTRIDE + warpN * 32 + nf * 8 + g;
                bfr[nf][0] = __float_as_uint(Bs[c0]);
                bfr[nf][1] = __float_as_uint(Bs[c0 + 4 * BSTRIDE]);
            }
            #pragma unroll
            for (int mf = 0; mf < 4; mf++)
                #pragma unroll
                for (int nf = 0; nf < 4; nf++)
                    mma_tf32(acc[mf][nf],
                             af[mf][0], af[mf][1], af[mf][2], af[mf][3],
                             bfr[nf][0], bfr[nf][1]);
        }

        if (more) pack(1 - stage);
        __syncthreads();
    }

    // epilogue
    #pragma unroll
    for (int nf = 0; nf < 4; nf++) {
        const int n0 = tileN + warpN * 32 + nf * 8 + t * 2;
        const float bv0 = bias[n0];
        const float bv1 = bias[n0 + 1];
        float inv = 0.f;
        if (QKV) {
            const int ip = (n0 & 63) >> 1;
            inv = powf(10000.0f, -(float)ip / 32.0f);
        }
        #pragma unroll
        for (int mf = 0; mf < 4; mf++) {
            float4 a = acc[mf][nf];
            const int r0 = tileM + warpM * 64 + mf * 16 + g;
            float x0 = a.x + bv0, x1 = a.y + bv1;
            float y0 = a.z + bv0, y1 = a.w + bv1;
            if (!QKV) {
                *(float2*)&out[(size_t)r0 * C + n0]       = make_float2(x0, x1);
                *(float2*)&out[(size_t)(r0 + 8) * C + n0] = make_float2(y0, y1);
            } else {
                const int bb = r0 / T;
                const int t0 = r0 % T;
                const int h  = n0 >> 6;
                const int d0 = n0 & 63;
                if (sel < 2) {
                    float sn, cs;
                    sincosf((float)t0 * inv, &sn, &cs);
                    float u0 = x0 * cs - x1 * sn;
                    float u1 = x0 * sn + x1 * cs;
                    x0 = u0; x1 = u1;
                    sincosf((float)(t0 + 8) * inv, &sn, &cs);
                    float w0 = y0 * cs - y1 * sn;
                    float w1 = y0 * sn + y1 * cs;
                    y0 = w0; y1 = w1;
                }
                float* dst = out + (((size_t)bb * NH + h) * T + t0) * HS + d0;
                *(float2*)dst            = make_float2(x0, x1);
                *(float2*)(dst + 8 * HS) = make_float2(y0, y1);
            }
        }
    }
}

// ---------------------------------------------------------------------------
// Tensor-core flash attention (unchanged from round 4).
// ---------------------------------------------------------------------------
__global__ __launch_bounds__(128, 2)
void attn_tc()
{
    extern __shared__ float smp[];
    float* Khi = smp;            // 64*68
    float* Klo = smp + 4352;     // 64*68
    float* Vt  = smp + 8704;     // 64*68 (transposed: [dim][key])

    const int qt   = gridDim.x - 1 - blockIdx.x;   // big tiles first
    const int h    = blockIdx.y;
    const int bb   = blockIdx.z;
    const int tid  = threadIdx.x;
    const int lane = tid & 31;
    const int warp = tid >> 5;
    const int g    = lane >> 2;
    const int t    = lane & 3;

    const float* kbase = g_k + ((size_t)(bb * NH + h) * T) * HS;
    const float* vbase = g_v + ((size_t)(bb * NH + h) * T) * HS;
    const float* qbase = g_q + ((size_t)(bb * NH + h) * T + (size_t)qt * 64) * HS;

    const int rowL = warp * 16 + g;

    uint32_t qhi[8][4], qlo[8][4];
    #pragma unroll
    for (int ks = 0; ks < 8; ks++) {
        float a0 = qbase[(size_t)rowL * HS + ks * 8 + t] * 0.125f;
        float a1 = qbase[(size_t)(rowL + 8) * HS + ks * 8 + t] * 0.125f;
        float a2 = qbase[(size_t)rowL * HS + ks * 8 + t + 4] * 0.125f;
        float a3 = qbase[(size_t)(rowL + 8) * HS + ks * 8 + t + 4] * 0.125f;
        split_tf32(a0, qhi[ks][0], qlo[ks][0]);
        split_tf32(a1, qhi[ks][1], qlo[ks][1]);
        split_tf32(a2, qhi[ks][2], qlo[ks][2]);
        split_tf32(a3, qhi[ks][3], qlo[ks][3]);
    }

    float4 O[8];
    #pragma unroll
    for (int i = 0; i < 8; i++) O[i] = make_float4(0.f, 0.f, 0.f, 0.f);
    float m0 = -1e30f, m1 = -1e30f, l0 = 0.f, l1 = 0.f;

    for (int kt = 0; kt <= qt; kt++) {
        #pragma unroll
        for (int i = 0; i < 8; i++) {
            int idx = tid + i * 128;
            int key = idx >> 4;
            int d0  = (idx & 15) * 4;
            float4 kv = *(const float4*)&kbase[(size_t)(kt * 64 + key) * HS + d0];
            float hx = f2tf32(kv.x), hy = f2tf32(kv.y), hz = f2tf32(kv.z), hw = f2tf32(kv.w);
            *(float4*)&Khi[key * 68 + d0] = make_float4(hx, hy, hz, hw);
            *(float4*)&Klo[key * 68 + d0] = make_float4(
                f2tf32(kv.x - hx), f2tf32(kv.y - hy), f2tf32(kv.z - hz), f2tf32(kv.w - hw));
        }
        #pragma unroll
        for (int i = 0; i < 8; i++) {
            int idx = tid + i * 128;
            int key = idx & 63;
            int d0  = (idx >> 6) * 4;
            float4 vv = *(const float4*)&vbase[(size_t)(kt * 64 + key) * HS + d0];
            Vt[(d0 + 0) * 68 + key] = f2tf32(vv.x);
            Vt[(d0 + 1) * 68 + key] = f2tf32(vv.y);
            Vt[(d0 + 2) * 68 + key] = f2tf32(vv.z);
            Vt[(d0 + 3) * 68 + key] = f2tf32(vv.w);
        }
        __syncthreads();

        float4 S[8];
        #pragma unroll
        for (int i = 0; i < 8; i++) S[i] = make_float4(0.f, 0.f, 0.f, 0.f);

        #pragma unroll
        for (int ks = 0; ks < 8; ks++) {
            #pragma unroll
            for (int n8 = 0; n8 < 8; n8++) {
                const int off = (n8 * 8 + g) * 68 + ks * 8 + t;
                uint32_t bh0 = __float_as_uint(Khi[off]);
                uint32_t bh1 = __float_as_uint(Khi[off + 4]);
                uint32_t bl0 = __float_as_uint(Klo[off]);
                uint32_t bl1 = __float_as_uint(Klo[off + 4]);
                mma_tf32(S[n8], qhi[ks][0], qhi[ks][1], qhi[ks][2], qhi[ks][3], bh0, bh1);
                mma_tf32(S[n8], qhi[ks][0], qhi[ks][1], qhi[ks][2], qhi[ks][3], bl0, bl1);
                mma_tf32(S[n8], qlo[ks][0], qlo[ks][1], qlo[ks][2], qlo[ks][3], bh0, bh1);
            }
        }

        if (kt == qt) {
            #pragma unroll
            for (int n8 = 0; n8 < 8; n8++) {
                int c0 = n8 * 8 + 2 * t;
                if (c0     > rowL    ) S[n8].x = -1e30f;
                if (c0 + 1 > rowL    ) S[n8].y = -1e30f;
                if (c0     > rowL + 8) S[n8].z = -1e30f;
                if (c0 + 1 > rowL + 8) S[n8].w = -1e30f;
            }
        }

        float mx0 = -1e30f, mx1 = -1e30f;
        #pragma unroll
        for (int n8 = 0; n8 < 8; n8++) {
            mx0 = fmaxf(mx0, fmaxf(S[n8].x, S[n8].y));
            mx1 = fmaxf(mx1, fmaxf(S[n8].z, S[n8].w));
        }
        mx0 = fmaxf(mx0, __shfl_xor_sync(0xffffffffu, mx0, 1));
        mx0 = fmaxf(mx0, __shfl_xor_sync(0xffffffffu, mx0, 2));
        mx1 = fmaxf(mx1, __shfl_xor_sync(0xffffffffu, mx1, 1));
        mx1 = fmaxf(mx1, __shfl_xor_sync(0xffffffffu, mx1, 2));

        float nm0 = fmaxf(m0, mx0);
        float nm1 = fmaxf(m1, mx1);
        float c0 = __expf(m0 - nm0);
        float c1 = __expf(m1 - nm1);
        m0 = nm0; m1 = nm1;
        l0 *= c0;  l1 *= c1;

        #pragma unroll
        for (int n8 = 0; n8 < 8; n8++) {
            S[n8].x = __expf(S[n8].x - nm0);
            S[n8].y = __expf(S[n8].y - nm0);
            S[n8].z = __expf(S[n8].z - nm1);
            S[n8].w = __expf(S[n8].w - nm1);
            l0 += S[n8].x + S[n8].y;
            l1 += S[n8].z + S[n8].w;
            O[n8].x *= c0; O[n8].y *= c0;
            O[n8].z *= c1; O[n8].w *= c1;
        }

        const int slBase = (lane & ~3) | (t >> 1);
        #pragma unroll
        for (int ks = 0; ks < 8; ks++) {
            float x0 = __shfl_sync(0xffffffffu, S[ks].x, slBase);
            float y0 = __shfl_sync(0xffffffffu, S[ks].y, slBase);
            float z0 = __shfl_sync(0xffffffffu, S[ks].z, slBase);
            float w0 = __shfl_sync(0xffffffffu, S[ks].w, slBase);
            float x1 = __shfl_sync(0xffffffffu, S[ks].x, slBase + 2);
            float y1 = __shfl_sync(0xffffffffu, S[ks].y, slBase + 2);
            float z1 = __shfl_sync(0xffffffffu, S[ks].z, slBase + 2);
            float w1 = __shfl_sync(0xffffffffu, S[ks].w, slBase + 2);
            uint32_t a0 = __float_as_uint(f2tf32((t & 1) ? y0 : x0));
            uint32_t a1 = __float_as_uint(f2tf32((t & 1) ? w0 : z0));
            uint32_t a2 = __float_as_uint(f2tf32((t & 1) ? y1 : x1));
            uint32_t a3 = __float_as_uint(f2tf32((t & 1) ? w1 : z1));

            #pragma unroll
            for (int n8 = 0; n8 < 8; n8++) {
                const int off = (n8 * 8 + g) * 68 + ks * 8 + t;
                uint32_t b0 = __float_as_uint(Vt[off]);
                uint32_t b1 = __float_as_uint(Vt[off + 4]);
                mma_tf32(O[n8], a0, a1, a2, a3, b0, b1);
            }
        }
        __syncthreads();
    }

    l0 += __shfl_xor_sync(0xffffffffu, l0, 1);
    l0 += __shfl_xor_sync(0xffffffffu, l0, 2);
    l1 += __shfl_xor_sync(0xffffffffu, l1, 1);
    l1 += __shfl_xor_sync(0xffffffffu, l1, 2);
    const float i0 = 1.0f / l0;
    const float i1 = 1.0f / l1;

    float* ob = g_att + ((size_t)bb * T + (size_t)qt * 64 + rowL) * C + h * 64;
    #pragma unroll
    for (int n8 = 0; n8 < 8; n8++) {
        *(float2*)&ob[n8 * 8 + 2 * t]         = make_float2(O[n8].x * i0, O[n8].y * i0);
        *(float2*)&ob[8 * C + n8 * 8 + 2 * t] = make_float2(O[n8].z * i1, O[n8].w * i1);
    }
}

// ---------------------------------------------------------------------------
extern "C" void kernel_launch(void* const* d_in, const int* in_sizes, int n_in,
                              void* d_out, int out_size)
{
    const float* x  = (const float*)d_in[0];
    const float* Wq = (const float*)d_in[1];
    const float* bq = (const float*)d_in[2];
    const float* Wk = (const float*)d_in[3];
    const float* bk = (const float*)d_in[4];
    const float* Wv = (const float*)d_in[5];
    const float* bv = (const float*)d_in[6];
    const float* Wp = (const float*)d_in[7];
    const float* bp = (const float*)d_in[8];
    float* out = (float*)d_out;

    const int GEMM_SMEM = 2 * STAGE_FLOATS * sizeof(float);    // 71680 B
    const int ATTN_SMEM = 3 * 64 * 68 * sizeof(float);         // 52224 B

    cudaFuncSetAttribute(gemm_tc<1>, cudaFuncAttributeMaxDynamicSharedMemorySize, GEMM_SMEM);
    cudaFuncSetAttribute(gemm_tc<0>, cudaFuncAttributeMaxDynamicSharedMemorySize, GEMM_SMEM);
    cudaFuncSetAttribute(attn_tc,    cudaFuncAttributeMaxDynamicSharedMemorySize, ATTN_SMEM);

    dim3 gq(24, M / 128);   // fused QKV: 24 x 64
    gemm_tc<1><<<gq, 256, GEMM_SMEM>>>(x, Wq, Wk, Wv, bq, bk, bv, nullptr);

    dim3 ga(T / 64, NH, Bz);   // 32 x 16 x 4
    attn_tc<<<ga, 128, ATTN_SMEM>>>();

    dim3 gp(8, M / 128);    // 8 x 64
    gemm_tc<0><<<gp, 256, GEMM_SMEM>>>(nullptr, Wp, nullptr, nullptr, bp, nullptr, nullptr, out);
}

// round 6
// speedup vs baseline: 5.6159x; 1.3000x over previous
#include <cuda_runtime.h>
#include <math.h>
#include <stdint.h>

#define Bz 4
#define T 2048
#define C 1024
#define NH 16
#define HS 64
#define M (Bz*T)

#define ASTRIDE 36
#define BSTRIDE 136
#define STAGE_FLOATS (4608 + 4352)   // A 128x36 + B 32x136

// Scratch (allocation-free rule: __device__ globals)
__device__ float g_q[Bz*NH*T*HS];   // [B,NH,T,HS] fp32 (full precision)
__device__ float g_k[Bz*NH*T*HS];   // [B,NH,T,HS] tf32-rounded
__device__ float g_v[Bz*NH*T*HS];   // [B,NH,HS,T] tf32-rounded, TRANSPOSED
__device__ float g_att[M*C];        // [B,T,C] tf32-rounded
__device__ float g_x [M*C];         // tf32-rounded X
__device__ float g_wq[C*C];
__device__ float g_wk[C*C];
__device__ float g_wv[C*C];
__device__ float g_wp[C*C];

// ---------------------------------------------------------------------------
// helpers
// ---------------------------------------------------------------------------
__device__ __forceinline__ float f2tf32(float f) {
    uint32_t u;
    asm("cvt.rna.tf32.f32 %0, %1;" : "=r"(u) : "f"(f));
    return __uint_as_float(u);
}

__device__ __forceinline__ void split_tf32(float v, uint32_t &hi, uint32_t &lo) {
    float h = f2tf32(v);
    hi = __float_as_uint(h);
    lo = __float_as_uint(f2tf32(v - h));
}

__device__ __forceinline__ void mma_tf32(float4 &d,
    uint32_t a0, uint32_t a1, uint32_t a2, uint32_t a3,
    uint32_t b0, uint32_t b1)
{
    asm volatile(
        "mma.sync.aligned.m16n8k8.row.col.f32.tf32.tf32.f32 "
        "{%0,%1,%2,%3}, {%4,%5,%6,%7}, {%8,%9}, {%0,%1,%2,%3};\n"
        : "+f"(d.x), "+f"(d.y), "+f"(d.z), "+f"(d.w)
        : "r"(a0), "r"(a1), "r"(a2), "r"(a3), "r"(b0), "r"(b1));
}

__device__ __forceinline__ void cp16(float* smem_dst, const float* gsrc) {
    uint32_t s = (uint32_t)__cvta_generic_to_shared(smem_dst);
    asm volatile("cp.async.cg.shared.global [%0], [%1], 16;" :: "r"(s), "l"(gsrc));
}
#define CP_COMMIT()  asm volatile("cp.async.commit_group;" ::: "memory")
#define CP_WAIT(N)   asm volatile("cp.async.wait_group %0;" :: "n"(N) : "memory")

// ---------------------------------------------------------------------------
// pre-conversion: round an array to tf32 (rna), exact n % 1024 == 0
// ---------------------------------------------------------------------------
__global__ void cvt_tf32(const float* __restrict__ s, float* __restrict__ d) {
    int i = (blockIdx.x * 256 + threadIdx.x) * 4;
    float4 v = *(const float4*)&s[i];
    *(float4*)&d[i] = make_float4(f2tf32(v.x), f2tf32(v.y), f2tf32(v.z), f2tf32(v.w));
}

// ---------------------------------------------------------------------------
// Tensor-core GEMM, cp.async double-buffered, NO in-loop conversions
// (X and W pre-rounded to tf32 bit patterns).
// QKV=1: fused Q/K/V (grid.x=24), epilogue bias+RoPE+scatter;
//        K rounded tf32; V rounded + transposed [B,NH,HS,T].
// QKV=0: output projection from g_att.
// ---------------------------------------------------------------------------
template<int QKV>
__global__ __launch_bounds__(256, 2)
void gemm_tc(const float* __restrict__ b0p,
             const float* __restrict__ b1p,
             const float* __restrict__ b2p,
             float* __restrict__ outp)
{
    extern __shared__ float smp[];   // 2 stages x STAGE_FLOATS

    const float* X;
    const float* W;
    const float* bias;
    float* out;
    int sel, tileN;
    if (QKV) {
        X = g_x;
        sel = blockIdx.x >> 3;
        tileN = (blockIdx.x & 7) * 128;
        W    = (sel == 0) ? g_wq : (sel == 1) ? g_wk : g_wv;
        bias = (sel == 0) ? b0p  : (sel == 1) ? b1p  : b2p;
        out  = (sel == 0) ? g_q  : (sel == 1) ? g_k  : g_v;
    } else {
        X = g_att;
        sel = 3;
        tileN = blockIdx.x * 128;
        W = g_wp; bias = b0p; out = outp;
    }

    const int tid   = threadIdx.x;
    const int lane  = tid & 31;
    const int warp  = tid >> 5;
    const int warpM = warp >> 2;
    const int warpN = warp & 3;
    const int g     = lane >> 2;
    const int t     = lane & 3;

    const int tileM = blockIdx.y * 128;

    const int am = tid >> 3;          // +32*i
    const int ac = (tid & 7) * 4;
    const int bk = tid >> 5;          // +8*i
    const int bc = (tid & 31) * 4;

    float4 acc[4][4];
    #pragma unroll
    for (int i = 0; i < 4; i++)
        #pragma unroll
        for (int j = 0; j < 4; j++)
            acc[i][j] = make_float4(0.f, 0.f, 0.f, 0.f);

    auto pref = [&](int s, int k0) {
        float* As = smp + s * STAGE_FLOATS;
        float* Bs = As + 4608;
        #pragma unroll
        for (int i = 0; i < 4; i++) {
            cp16(&As[(am + 32 * i) * ASTRIDE + ac],
                 &X[(size_t)(tileM + am + 32 * i) * C + k0 + ac]);
            cp16(&Bs[(bk + 8 * i) * BSTRIDE + bc],
                 &W[(size_t)(k0 + bk + 8 * i) * C + tileN + bc]);
        }
    };

    pref(0, 0);
    CP_COMMIT();

    for (int it = 0; it < 32; it++) {
        if (it < 31) {
            pref((it + 1) & 1, (it + 1) * 32);
            CP_COMMIT();
            CP_WAIT(1);
        } else {
            CP_WAIT(0);
        }
        __syncthreads();

        const float* As = smp + (it & 1) * STAGE_FLOATS;
        const float* Bs = As + 4608;

        #pragma unroll
        for (int ks = 0; ks < 4; ks++) {
            uint32_t af[4][4];
            uint32_t bfr[4][2];
            #pragma unroll
            for (int mf = 0; mf < 4; mf++) {
                const int r0 = (warpM * 64 + mf * 16 + g) * ASTRIDE + ks * 8 + t;
                af[mf][0] = __float_as_uint(As[r0]);
                af[mf][1] = __float_as_uint(As[r0 + 8 * ASTRIDE]);
                af[mf][2] = __float_as_uint(As[r0 + 4]);
                af[mf][3] = __float_as_uint(As[r0 + 8 * ASTRIDE + 4]);
            }
            #pragma unroll
            for (int nf = 0; nf < 4; nf++) {
                const int c0 = (ks * 8 + t) * BSTRIDE + warpN * 32 + nf * 8 + g;
                bfr[nf][0] = __float_as_uint(Bs[c0]);
                bfr[nf][1] = __float_as_uint(Bs[c0 + 4 * BSTRIDE]);
            }
            #pragma unroll
            for (int mf = 0; mf < 4; mf++)
                #pragma unroll
                for (int nf = 0; nf < 4; nf++)
                    mma_tf32(acc[mf][nf],
                             af[mf][0], af[mf][1], af[mf][2], af[mf][3],
                             bfr[nf][0], bfr[nf][1]);
        }
        __syncthreads();
    }

    // epilogue
    #pragma unroll
    for (int nf = 0; nf < 4; nf++) {
        const int n0 = tileN + warpN * 32 + nf * 8 + t * 2;
        const float bv0 = bias[n0];
        const float bv1 = bias[n0 + 1];
        float inv = 0.f;
        if (QKV) {
            const int ip = (n0 & 63) >> 1;
            inv = powf(10000.0f, -(float)ip / 32.0f);
        }
        #pragma unroll
        for (int mf = 0; mf < 4; mf++) {
            float4 a = acc[mf][nf];
            const int r0 = tileM + warpM * 64 + mf * 16 + g;
            float x0 = a.x + bv0, x1 = a.y + bv1;
            float y0 = a.z + bv0, y1 = a.w + bv1;
            if (!QKV) {
                *(float2*)&out[(size_t)r0 * C + n0]       = make_float2(x0, x1);
                *(float2*)&out[(size_t)(r0 + 8) * C + n0] = make_float2(y0, y1);
            } else {
                const int bb = r0 / T;
                const int t0 = r0 % T;
                const int h  = n0 >> 6;
                const int d0 = n0 & 63;
                if (sel < 2) {   // RoPE for Q and K
                    float sn, cs;
                    sincosf((float)t0 * inv, &sn, &cs);
                    float u0 = x0 * cs - x1 * sn;
                    float u1 = x0 * sn + x1 * cs;
                    x0 = u0; x1 = u1;
                    sincosf((float)(t0 + 8) * inv, &sn, &cs);
                    float w0 = y0 * cs - y1 * sn;
                    float w1 = y0 * sn + y1 * cs;
                    y0 = w0; y1 = w1;
                }
                if (sel == 0) {
                    float* dst = out + (((size_t)bb * NH + h) * T + t0) * HS + d0;
                    *(float2*)dst            = make_float2(x0, x1);
                    *(float2*)(dst + 8 * HS) = make_float2(y0, y1);
                } else if (sel == 1) {
                    float* dst = out + (((size_t)bb * NH + h) * T + t0) * HS + d0;
                    *(float2*)dst            = make_float2(f2tf32(x0), f2tf32(x1));
                    *(float2*)(dst + 8 * HS) = make_float2(f2tf32(y0), f2tf32(y1));
                } else {   // V: transposed [B,NH,HS,T], tf32
                    float* dst = out + (((size_t)bb * NH + h) * HS + d0) * T + t0;
                    dst[0]     = f2tf32(x0);
                    dst[T]     = f2tf32(x1);
                    dst[8]     = f2tf32(y0);
                    dst[T + 8] = f2tf32(y1);
                }
            }
        }
    }
}

// ---------------------------------------------------------------------------
// Tensor-core flash attention.
// QK: 2-term (Q split hi/lo in regs, K tf32 in smem). PV: plain tf32.
// K/V tiles loaded via cp.async, double-buffered (K already tf32/rope'd,
// V already tf32 + transposed in gmem). Block: 64 q rows, 4 warps.
// smem: 2 stages x (Khi [key][68] + Vt [dim][68]).
// ---------------------------------------------------------------------------
__global__ __launch_bounds__(128, 2)
void attn_tc()
{
    extern __shared__ float smp[];   // 2 x 8704 floats

    const int qt   = gridDim.x - 1 - blockIdx.x;   // big tiles first
    const int h    = blockIdx.y;
    const int bb   = blockIdx.z;
    const int tid  = threadIdx.x;
    const int lane = tid & 31;
    const int warp = tid >> 5;
    const int g    = lane >> 2;
    const int t    = lane & 3;

    const float* kbase = g_k + (size_t)(bb * NH + h) * T * HS;      // [key][dim]
    const float* vbase = g_v + (size_t)(bb * NH + h) * HS * T;      // [dim][key]
    const float* qbase = g_q + ((size_t)(bb * NH + h) * T + (size_t)qt * 64) * HS;

    const int rowL = warp * 16 + g;

    uint32_t qhi[8][4], qlo[8][4];
    #pragma unroll
    for (int ks = 0; ks < 8; ks++) {
        float a0 = qbase[(size_t)rowL * HS + ks * 8 + t] * 0.125f;
        float a1 = qbase[(size_t)(rowL + 8) * HS + ks * 8 + t] * 0.125f;
        float a2 = qbase[(size_t)rowL * HS + ks * 8 + t + 4] * 0.125f;
        float a3 = qbase[(size_t)(rowL + 8) * HS + ks * 8 + t + 4] * 0.125f;
        split_tf32(a0, qhi[ks][0], qlo[ks][0]);
        split_tf32(a1, qhi[ks][1], qlo[ks][1]);
        split_tf32(a2, qhi[ks][2], qlo[ks][2]);
        split_tf32(a3, qhi[ks][3], qlo[ks][3]);
    }

    auto pref = [&](int s, int kt) {
        float* Kh = smp + s * 8704;
        float* Vv = Kh + 4352;
        #pragma unroll
        for (int i = 0; i < 8; i++) {
            int idx = tid + i * 128;
            int r  = idx >> 4;
            int c4 = (idx & 15) * 4;
            cp16(&Kh[r * 68 + c4], kbase + (size_t)(kt * 64 + r) * HS + c4);
            cp16(&Vv[r * 68 + c4], vbase + (size_t)r * T + kt * 64 + c4);
        }
    };

    float4 O[8];
    #pragma unroll
    for (int i = 0; i < 8; i++) O[i] = make_float4(0.f, 0.f, 0.f, 0.f);
    float m0 = -1e30f, m1 = -1e30f, l0 = 0.f, l1 = 0.f;

    pref(0, 0);
    CP_COMMIT();

    for (int kt = 0; kt <= qt; kt++) {
        if (kt < qt) {
            pref((kt + 1) & 1, kt + 1);
            CP_COMMIT();
            CP_WAIT(1);
        } else {
            CP_WAIT(0);
        }
        __syncthreads();

        const float* Khi = smp + (kt & 1) * 8704;
        const float* Vt  = Khi + 4352;

        // --- scores S = Q Kt (2-term: (qhi+qlo) x Khi) ---
        float4 S[8];
        #pragma unroll
        for (int i = 0; i < 8; i++) S[i] = make_float4(0.f, 0.f, 0.f, 0.f);

        #pragma unroll
        for (int ks = 0; ks < 8; ks++) {
            #pragma unroll
            for (int n8 = 0; n8 < 8; n8++) {
                const int off = (n8 * 8 + g) * 68 + ks * 8 + t;
                uint32_t bh0 = __float_as_uint(Khi[off]);
                uint32_t bh1 = __float_as_uint(Khi[off + 4]);
                mma_tf32(S[n8], qhi[ks][0], qhi[ks][1], qhi[ks][2], qhi[ks][3], bh0, bh1);
                mma_tf32(S[n8], qlo[ks][0], qlo[ks][1], qlo[ks][2], qlo[ks][3], bh0, bh1);
            }
        }

        if (kt == qt) {
            #pragma unroll
            for (int n8 = 0; n8 < 8; n8++) {
                int c0 = n8 * 8 + 2 * t;
                if (c0     > rowL    ) S[n8].x = -1e30f;
                if (c0 + 1 > rowL    ) S[n8].y = -1e30f;
                if (c0     > rowL + 8) S[n8].z = -1e30f;
                if (c0 + 1 > rowL + 8) S[n8].w = -1e30f;
            }
        }

        float mx0 = -1e30f, mx1 = -1e30f;
        #pragma unroll
        for (int n8 = 0; n8 < 8; n8++) {
            mx0 = fmaxf(mx0, fmaxf(S[n8].x, S[n8].y));
            mx1 = fmaxf(mx1, fmaxf(S[n8].z, S[n8].w));
        }
        mx0 = fmaxf(mx0, __shfl_xor_sync(0xffffffffu, mx0, 1));
        mx0 = fmaxf(mx0, __shfl_xor_sync(0xffffffffu, mx0, 2));
        mx1 = fmaxf(mx1, __shfl_xor_sync(0xffffffffu, mx1, 1));
        mx1 = fmaxf(mx1, __shfl_xor_sync(0xffffffffu, mx1, 2));

        float nm0 = fmaxf(m0, mx0);
        float nm1 = fmaxf(m1, mx1);
        float c0 = __expf(m0 - nm0);
        float c1 = __expf(m1 - nm1);
        m0 = nm0; m1 = nm1;
        l0 *= c0;  l1 *= c1;

        #pragma unroll
        for (int n8 = 0; n8 < 8; n8++) {
            S[n8].x = __expf(S[n8].x - nm0);
            S[n8].y = __expf(S[n8].y - nm0);
            S[n8].z = __expf(S[n8].z - nm1);
            S[n8].w = __expf(S[n8].w - nm1);
            l0 += S[n8].x + S[n8].y;
            l1 += S[n8].z + S[n8].w;
            O[n8].x *= c0; O[n8].y *= c0;
            O[n8].z *= c1; O[n8].w *= c1;
        }

        // --- O += P V ---
        const int slBase = (lane & ~3) | (t >> 1);
        #pragma unroll
        for (int ks = 0; ks < 8; ks++) {
            float x0 = __shfl_sync(0xffffffffu, S[ks].x, slBase);
            float y0 = __shfl_sync(0xffffffffu, S[ks].y, slBase);
            float z0 = __shfl_sync(0xffffffffu, S[ks].z, slBase);
            float w0 = __shfl_sync(0xffffffffu, S[ks].w, slBase);
            float x1 = __shfl_sync(0xffffffffu, S[ks].x, slBase + 2);
            float y1 = __shfl_sync(0xffffffffu, S[ks].y, slBase + 2);
            float z1 = __shfl_sync(0xffffffffu, S[ks].z, slBase + 2);
            float w1 = __shfl_sync(0xffffffffu, S[ks].w, slBase + 2);
            uint32_t a0 = __float_as_uint(f2tf32((t & 1) ? y0 : x0));
            uint32_t a1 = __float_as_uint(f2tf32((t & 1) ? w0 : z0));
            uint32_t a2 = __float_as_uint(f2tf32((t & 1) ? y1 : x1));
            uint32_t a3 = __float_as_uint(f2tf32((t & 1) ? w1 : z1));

            #pragma unroll
            for (int n8 = 0; n8 < 8; n8++) {
                const int off = (n8 * 8 + g) * 68 + ks * 8 + t;
                uint32_t b0 = __float_as_uint(Vt[off]);
                uint32_t b1 = __float_as_uint(Vt[off + 4]);
                mma_tf32(O[n8], a0, a1, a2, a3, b0, b1);
            }
        }
        __syncthreads();
    }

    l0 += __shfl_xor_sync(0xffffffffu, l0, 1);
    l0 += __shfl_xor_sync(0xffffffffu, l0, 2);
    l1 += __shfl_xor_sync(0xffffffffu, l1, 1);
    l1 += __shfl_xor_sync(0xffffffffu, l1, 2);
    const float i0 = 1.0f / l0;
    const float i1 = 1.0f / l1;

    // write tf32-rounded so proj GEMM needs no conversion
    float* ob = g_att + ((size_t)bb * T + (size_t)qt * 64 + rowL) * C + h * 64;
    #pragma unroll
    for (int n8 = 0; n8 < 8; n8++) {
        *(float2*)&ob[n8 * 8 + 2 * t] =
            make_float2(f2tf32(O[n8].x * i0), f2tf32(O[n8].y * i0));
        *(float2*)&ob[8 * C + n8 * 8 + 2 * t] =
            make_float2(f2tf32(O[n8].z * i1), f2tf32(O[n8].w * i1));
    }
}

// ---------------------------------------------------------------------------
extern "C" void kernel_launch(void* const* d_in, const int* in_sizes, int n_in,
                              void* d_out, int out_size)
{
    const float* x  = (const float*)d_in[0];
    const float* Wq = (const float*)d_in[1];
    const float* bq = (const float*)d_in[2];
    const float* Wk = (const float*)d_in[3];
    const float* bk = (const float*)d_in[4];
    const float* Wv = (const float*)d_in[5];
    const float* bv = (const float*)d_in[6];
    const float* Wp = (const float*)d_in[7];
    const float* bp = (const float*)d_in[8];
    float* out = (float*)d_out;

    float* d_gx;  cudaGetSymbolAddress((void**)&d_gx,  g_x);
    float* d_gwq; cudaGetSymbolAddress((void**)&d_gwq, g_wq);
    float* d_gwk; cudaGetSymbolAddress((void**)&d_gwk, g_wk);
    float* d_gwv; cudaGetSymbolAddress((void**)&d_gwv, g_wv);
    float* d_gwp; cudaGetSymbolAddress((void**)&d_gwp, g_wp);

    const int GEMM_SMEM = 2 * STAGE_FLOATS * sizeof(float);   // 71680 B
    const int ATTN_SMEM = 2 * 8704 * sizeof(float);           // 69632 B

    cudaFuncSetAttribute(gemm_tc<1>, cudaFuncAttributeMaxDynamicSharedMemorySize, GEMM_SMEM);
    cudaFuncSetAttribute(gemm_tc<0>, cudaFuncAttributeMaxDynamicSharedMemorySize, GEMM_SMEM);
    cudaFuncSetAttribute(attn_tc,    cudaFuncAttributeMaxDynamicSharedMemorySize, ATTN_SMEM);

    // pre-round inputs to tf32 (rna)
    cvt_tf32<<<M*C/1024, 256>>>(x,  d_gx);
    cvt_tf32<<<C*C/1024, 256>>>(Wq, d_gwq);
    cvt_tf32<<<C*C/1024, 256>>>(Wk, d_gwk);
    cvt_tf32<<<C*C/1024, 256>>>(Wv, d_gwv);
    cvt_tf32<<<C*C/1024, 256>>>(Wp, d_gwp);

    dim3 gq(24, M / 128);   // fused QKV
    gemm_tc<1><<<gq, 256, GEMM_SMEM>>>(bq, bk, bv, nullptr);

    dim3 ga(T / 64, NH, Bz);
    attn_tc<<<ga, 128, ATTN_SMEM>>>();

    dim3 gp(8, M / 128);
    gemm_tc<0><<<gp, 256, GEMM_SMEM>>>(bp, nullptr, nullptr, out);
}

// round 8
// speedup vs baseline: 6.0133x; 1.0708x over previous
#include <cuda_runtime.h>
#include <math.h>
#include <stdint.h>

#define Bz 4
#define T 2048
#define C 1024
#define NH 16
#define HS 64
#define M (Bz*T)

#define ASTRIDE 36
#define BSTRIDE 136
#define STAGE_FLOATS (4608 + 4352)   // A 128x36 + B 32x136

// Scratch (allocation-free rule: __device__ globals)
__device__ float g_q[Bz*NH*T*HS];   // [B,NH,T,HS] fp32
__device__ float g_k[Bz*NH*T*HS];   // [B,NH,T,HS] tf32-rounded
__device__ float g_v[Bz*NH*T*HS];   // [B,NH,HS,T] tf32-rounded, transposed
__device__ float g_att[M*C];        // [B,T,C] tf32-rounded
__device__ float g_x [M*C];         // tf32-rounded X
__device__ float g_wq[C*C];
__device__ float g_wk[C*C];
__device__ float g_wv[C*C];
__device__ float g_wp[C*C];

// ---------------------------------------------------------------------------
__device__ __forceinline__ float f2tf32(float f) {
    uint32_t u;
    asm("cvt.rna.tf32.f32 %0, %1;" : "=r"(u) : "f"(f));
    return __uint_as_float(u);
}

__device__ __forceinline__ void mma_tf32(float4 &d,
    uint32_t a0, uint32_t a1, uint32_t a2, uint32_t a3,
    uint32_t b0, uint32_t b1)
{
    asm volatile(
        "mma.sync.aligned.m16n8k8.row.col.f32.tf32.tf32.f32 "
        "{%0,%1,%2,%3}, {%4,%5,%6,%7}, {%8,%9}, {%0,%1,%2,%3};\n"
        : "+f"(d.x), "+f"(d.y), "+f"(d.z), "+f"(d.w)
        : "r"(a0), "r"(a1), "r"(a2), "r"(a3), "r"(b0), "r"(b1));
}

__device__ __forceinline__ void cp16(float* smem_dst, const float* gsrc) {
    uint32_t s = (uint32_t)__cvta_generic_to_shared(smem_dst);
    asm volatile("cp.async.cg.shared.global [%0], [%1], 16;" :: "r"(s), "l"(gsrc));
}
#define CP_COMMIT()  asm volatile("cp.async.commit_group;" ::: "memory")
#define CP_WAIT(N)   asm volatile("cp.async.wait_group %0;" :: "n"(N) : "memory")

// ---------------------------------------------------------------------------
// merged pre-conversion: X (8192 blocks) + Wq/Wk/Wv/Wp (1024 each)
// ---------------------------------------------------------------------------
__global__ void cvt_all(const float* __restrict__ x,
                        const float* __restrict__ wq, const float* __restrict__ wk,
                        const float* __restrict__ wv, const float* __restrict__ wp)
{
    int b = blockIdx.x;
    const float* s; float* d; int off;
    if (b < 8192)       { s = x;  d = g_x;  off = b; }
    else if (b < 9216)  { s = wq; d = g_wq; off = b - 8192; }
    else if (b < 10240) { s = wk; d = g_wk; off = b - 9216; }
    else if (b < 11264) { s = wv; d = g_wv; off = b - 10240; }
    else                { s = wp; d = g_wp; off = b - 11264; }
    int i = (off * 256 + threadIdx.x) * 4;
    float4 v = *(const float4*)&s[i];
    *(float4*)&d[i] = make_float4(f2tf32(v.x), f2tf32(v.y), f2tf32(v.z), f2tf32(v.w));
}

// ---------------------------------------------------------------------------
// Tensor-core GEMM, 3-stage cp.async ring, one sync per k-iter.
// ---------------------------------------------------------------------------
template<int QKV>
__global__ __launch_bounds__(256, 2)
void gemm_tc(const float* __restrict__ b0p,
             const float* __restrict__ b1p,
             const float* __restrict__ b2p,
             float* __restrict__ outp)
{
    extern __shared__ float smp[];   // 3 stages x STAGE_FLOATS

    const float* X;
    const float* W;
    const float* bias;
    float* out;
    int sel, tileN;
    if (QKV) {
        X = g_x;
        sel = blockIdx.x >> 3;
        tileN = (blockIdx.x & 7) * 128;
        W    = (sel == 0) ? g_wq : (sel == 1) ? g_wk : g_wv;
        bias = (sel == 0) ? b0p  : (sel == 1) ? b1p  : b2p;
        out  = (sel == 0) ? g_q  : (sel == 1) ? g_k  : g_v;
    } else {
        X = g_att;
        sel = 3;
        tileN = blockIdx.x * 128;
        W = g_wp; bias = b0p; out = outp;
    }

    const int tid   = threadIdx.x;
    const int lane  = tid & 31;
    const int warp  = tid >> 5;
    const int warpM = warp >> 2;
    const int warpN = warp & 3;
    const int g     = lane >> 2;
    const int t     = lane & 3;

    const int tileM = blockIdx.y * 128;

    const int am = tid >> 3;
    const int ac = (tid & 7) * 4;
    const int bk = tid >> 5;
    const int bc = (tid & 31) * 4;

    float4 acc[4][4];
    #pragma unroll
    for (int i = 0; i < 4; i++)
        #pragma unroll
        for (int j = 0; j < 4; j++)
            acc[i][j] = make_float4(0.f, 0.f, 0.f, 0.f);

    auto pref = [&](int s, int k0) {
        float* As = smp + s * STAGE_FLOATS;
        float* Bs = As + 4608;
        #pragma unroll
        for (int i = 0; i < 4; i++) {
            cp16(&As[(am + 32 * i) * ASTRIDE + ac],
                 &X[(size_t)(tileM + am + 32 * i) * C + k0 + ac]);
            cp16(&Bs[(bk + 8 * i) * BSTRIDE + bc],
                 &W[(size_t)(k0 + bk + 8 * i) * C + tileN + bc]);
        }
    };

    pref(0, 0);  CP_COMMIT();
    pref(1, 32); CP_COMMIT();

    for (int it = 0; it < 32; it++) {
        if (it < 31) { CP_WAIT(1); } else { CP_WAIT(0); }
        __syncthreads();
        if (it + 2 < 32) { pref((it + 2) % 3, (it + 2) * 32); CP_COMMIT(); }

        const float* As = smp + (it % 3) * STAGE_FLOATS;
        const float* Bs = As + 4608;

        #pragma unroll
        for (int ks = 0; ks < 4; ks++) {
            uint32_t af[4][4];
            uint32_t bfr[4][2];
            #pragma unroll
            for (int mf = 0; mf < 4; mf++) {
                const int r0 = (warpM * 64 + mf * 16 + g) * ASTRIDE + ks * 8 + t;
                af[mf][0] = __float_as_uint(As[r0]);
                af[mf][1] = __float_as_uint(As[r0 + 8 * ASTRIDE]);
                af[mf][2] = __float_as_uint(As[r0 + 4]);
                af[mf][3] = __float_as_uint(As[r0 + 8 * ASTRIDE + 4]);
            }
            #pragma unroll
            for (int nf = 0; nf < 4; nf++) {
                const int c0 = (ks * 8 + t) * BSTRIDE + warpN * 32 + nf * 8 + g;
                bfr[nf][0] = __float_as_uint(Bs[c0]);
                bfr[nf][1] = __float_as_uint(Bs[c0 + 4 * BSTRIDE]);
            }
            #pragma unroll
            for (int mf = 0; mf < 4; mf++)
                #pragma unroll
                for (int nf = 0; nf < 4; nf++)
                    mma_tf32(acc[mf][nf],
                             af[mf][0], af[mf][1], af[mf][2], af[mf][3],
                             bfr[nf][0], bfr[nf][1]);
        }
    }

    // epilogue
    #pragma unroll
    for (int nf = 0; nf < 4; nf++) {
        const int n0 = tileN + warpN * 32 + nf * 8 + t * 2;
        const float bv0 = bias[n0];
        const float bv1 = bias[n0 + 1];
        float inv = 0.f;
        if (QKV) {
            const int ip = (n0 & 63) >> 1;
            inv = powf(10000.0f, -(float)ip / 32.0f);
        }
        #pragma unroll
        for (int mf = 0; mf < 4; mf++) {
            float4 a = acc[mf][nf];
            const int r0 = tileM + warpM * 64 + mf * 16 + g;
            float x0 = a.x + bv0, x1 = a.y + bv1;
            float y0 = a.z + bv0, y1 = a.w + bv1;
            if (!QKV) {
                *(float2*)&out[(size_t)r0 * C + n0]       = make_float2(x0, x1);
                *(float2*)&out[(size_t)(r0 + 8) * C + n0] = make_float2(y0, y1);
            } else {
                const int bb = r0 / T;
                const int t0 = r0 % T;
                const int h  = n0 >> 6;
                const int d0 = n0 & 63;
                if (sel < 2) {
                    float sn, cs;
                    sincosf((float)t0 * inv, &sn, &cs);
                    float u0 = x0 * cs - x1 * sn;
                    float u1 = x0 * sn + x1 * cs;
                    x0 = u0; x1 = u1;
                    sincosf((float)(t0 + 8) * inv, &sn, &cs);
                    float w0 = y0 * cs - y1 * sn;
                    float w1 = y0 * sn + y1 * cs;
                    y0 = w0; y1 = w1;
                }
                if (sel == 0) {
                    float* dst = out + (((size_t)bb * NH + h) * T + t0) * HS + d0;
                    *(float2*)dst            = make_float2(x0, x1);
                    *(float2*)(dst + 8 * HS) = make_float2(y0, y1);
                } else if (sel == 1) {
                    float* dst = out + (((size_t)bb * NH + h) * T + t0) * HS + d0;
                    *(float2*)dst            = make_float2(f2tf32(x0), f2tf32(x1));
                    *(float2*)(dst + 8 * HS) = make_float2(f2tf32(y0), f2tf32(y1));
                } else {
                    float* dst = out + (((size_t)bb * NH + h) * HS + d0) * T + t0;
                    dst[0]     = f2tf32(x0);
                    dst[T]     = f2tf32(x1);
                    dst[8]     = f2tf32(y0);
                    dst[T + 8] = f2tf32(y1);
                }
            }
        }
    }
}

// ---------------------------------------------------------------------------
// Flash attention: 128 q rows/block, 4 warps, 32 q rows per warp (2 m16 tiles)
// QK 1-term tf32, PV tf32. 3-stage cp.async ring for 64-key K/V tiles.
// smem per stage: K [64][68] + Vt [64][68].
// ---------------------------------------------------------------------------
__global__ __launch_bounds__(128, 2)
void attn_tc()
{
    extern __shared__ float smp[];   // 3 x 8704 floats

    const int qt   = gridDim.x - 1 - blockIdx.x;   // big tiles first
    const int h    = blockIdx.y;
    const int bb   = blockIdx.z;
    const int tid  = threadIdx.x;
    const int lane = tid & 31;
    const int warp = tid >> 5;
    const int g    = lane >> 2;
    const int t    = lane & 3;

    const float* kbase = g_k + (size_t)(bb * NH + h) * T * HS;   // [key][dim]
    const float* vbase = g_v + (size_t)(bb * NH + h) * HS * T;   // [dim][key]
    const float* qbase = g_q + ((size_t)(bb * NH + h) * T + (size_t)qt * 128) * HS;

    // two m16 A-tiles per warp: local row base = warp*32 + a*16
    uint32_t qa[2][8][4];
    #pragma unroll
    for (int a = 0; a < 2; a++) {
        const int base = warp * 32 + a * 16;
        #pragma unroll
        for (int ks = 0; ks < 8; ks++) {
            qa[a][ks][0] = __float_as_uint(f2tf32(qbase[(size_t)(base + g)     * HS + ks * 8 + t]     * 0.125f));
            qa[a][ks][1] = __float_as_uint(f2tf32(qbase[(size_t)(base + g + 8) * HS + ks * 8 + t]     * 0.125f));
            qa[a][ks][2] = __float_as_uint(f2tf32(qbase[(size_t)(base + g)     * HS + ks * 8 + t + 4] * 0.125f));
            qa[a][ks][3] = __float_as_uint(f2tf32(qbase[(size_t)(base + g + 8) * HS + ks * 8 + t + 4] * 0.125f));
        }
    }

    auto pref = [&](int s, int kt) {
        float* Kh = smp + s * 8704;
        float* Vv = Kh + 4352;
        #pragma unroll
        for (int i = 0; i < 8; i++) {
            int idx = tid + i * 128;
            int r  = idx >> 4;
            int c4 = (idx & 15) * 4;
            cp16(&Kh[r * 68 + c4], kbase + (size_t)(kt * 64 + r) * HS + c4);
            cp16(&Vv[r * 68 + c4], vbase + (size_t)r * T + kt * 64 + c4);
        }
    };

    float4 O[2][8];
    float  m[2][2], l[2][2];
    #pragma unroll
    for (int a = 0; a < 2; a++) {
        #pragma unroll
        for (int i = 0; i < 8; i++) O[a][i] = make_float4(0.f, 0.f, 0.f, 0.f);
        m[a][0] = m[a][1] = -1e30f;
        l[a][0] = l[a][1] = 0.f;
    }

    const int ktmax = qt * 2 + 1;

    pref(0, 0); CP_COMMIT();
    pref(1, 1); CP_COMMIT();

    for (int kt = 0; kt <= ktmax; kt++) {
        if (kt < ktmax) { CP_WAIT(1); } else { CP_WAIT(0); }
        __syncthreads();
        if (kt + 2 <= ktmax) { pref((kt + 2) % 3, kt + 2); CP_COMMIT(); }

        const float* Khi = smp + (kt % 3) * 8704;
        const float* Vt  = Khi + 4352;

        // --- scores: both A-tiles share each B-fragment load ---
        float4 S[2][8];
        #pragma unroll
        for (int a = 0; a < 2; a++)
            #pragma unroll
            for (int i = 0; i < 8; i++) S[a][i] = make_float4(0.f, 0.f, 0.f, 0.f);

        #pragma unroll
        for (int ks = 0; ks < 8; ks++) {
            #pragma unroll
            for (int n8 = 0; n8 < 8; n8++) {
                const int off = (n8 * 8 + g) * 68 + ks * 8 + t;
                uint32_t b0 = __float_as_uint(Khi[off]);
                uint32_t b1 = __float_as_uint(Khi[off + 4]);
                mma_tf32(S[0][n8], qa[0][ks][0], qa[0][ks][1], qa[0][ks][2], qa[0][ks][3], b0, b1);
                mma_tf32(S[1][n8], qa[1][ks][0], qa[1][ks][1], qa[1][ks][2], qa[1][ks][3], b0, b1);
            }
        }

        // --- causal mask (mask whenever tile max key exceeds a-tile FIRST row) ---
        #pragma unroll
        for (int a = 0; a < 2; a++) {
            const int base = qt * 128 + warp * 32 + a * 16;     // global row base
            if (kt * 64 + 63 > base) {
                const int r0 = base + g;
                #pragma unroll
                for (int n8 = 0; n8 < 8; n8++) {
                    int c0 = kt * 64 + n8 * 8 + 2 * t;
                    if (c0     > r0    ) S[a][n8].x = -1e30f;
                    if (c0 + 1 > r0    ) S[a][n8].y = -1e30f;
                    if (c0     > r0 + 8) S[a][n8].z = -1e30f;
                    if (c0 + 1 > r0 + 8) S[a][n8].w = -1e30f;
                }
            }
        }

        // --- online softmax per a-tile ---
        #pragma unroll
        for (int a = 0; a < 2; a++) {
            float mx0 = -1e30f, mx1 = -1e30f;
            #pragma unroll
            for (int n8 = 0; n8 < 8; n8++) {
                mx0 = fmaxf(mx0, fmaxf(S[a][n8].x, S[a][n8].y));
                mx1 = fmaxf(mx1, fmaxf(S[a][n8].z, S[a][n8].w));
            }
            mx0 = fmaxf(mx0, __shfl_xor_sync(0xffffffffu, mx0, 1));
            mx0 = fmaxf(mx0, __shfl_xor_sync(0xffffffffu, mx0, 2));
            mx1 = fmaxf(mx1, __shfl_xor_sync(0xffffffffu, mx1, 1));
            mx1 = fmaxf(mx1, __shfl_xor_sync(0xffffffffu, mx1, 2));

            float nm0 = fmaxf(m[a][0], mx0);
            float nm1 = fmaxf(m[a][1], mx1);
            float c0 = __expf(m[a][0] - nm0);
            float c1 = __expf(m[a][1] - nm1);
            m[a][0] = nm0; m[a][1] = nm1;
            l[a][0] *= c0; l[a][1] *= c1;

            #pragma unroll
            for (int n8 = 0; n8 < 8; n8++) {
                S[a][n8].x = __expf(S[a][n8].x - nm0);
                S[a][n8].y = __expf(S[a][n8].y - nm0);
                S[a][n8].z = __expf(S[a][n8].z - nm1);
                S[a][n8].w = __expf(S[a][n8].w - nm1);
                l[a][0] += S[a][n8].x + S[a][n8].y;
                l[a][1] += S[a][n8].z + S[a][n8].w;
                O[a][n8].x *= c0; O[a][n8].y *= c0;
                O[a][n8].z *= c1; O[a][n8].w *= c1;
            }
        }

        // --- O += P V (B-fragments shared across the two a-tiles) ---
        const int slBase = (lane & ~3) | (t >> 1);
        #pragma unroll
        for (int ks = 0; ks < 8; ks++) {
            uint32_t pa[2][4];
            #pragma unroll
            for (int a = 0; a < 2; a++) {
                float x0 = __shfl_sync(0xffffffffu, S[a][ks].x, slBase);
                float y0 = __shfl_sync(0xffffffffu, S[a][ks].y, slBase);
                float z0 = __shfl_sync(0xffffffffu, S[a][ks].z, slBase);
                float w0 = __shfl_sync(0xffffffffu, S[a][ks].w, slBase);
                float x1 = __shfl_sync(0xffffffffu, S[a][ks].x, slBase + 2);
                float y1 = __shfl_sync(0xffffffffu, S[a][ks].y, slBase + 2);
                float z1 = __shfl_sync(0xffffffffu, S[a][ks].z, slBase + 2);
                float w1 = __shfl_sync(0xffffffffu, S[a][ks].w, slBase + 2);
                pa[a][0] = __float_as_uint(f2tf32((t & 1) ? y0 : x0));
                pa[a][1] = __float_as_uint(f2tf32((t & 1) ? w0 : z0));
                pa[a][2] = __float_as_uint(f2tf32((t & 1) ? y1 : x1));
                pa[a][3] = __float_as_uint(f2tf32((t & 1) ? w1 : z1));
            }
            #pragma unroll
            for (int n8 = 0; n8 < 8; n8++) {
                const int off = (n8 * 8 + g) * 68 + ks * 8 + t;
                uint32_t b0 = __float_as_uint(Vt[off]);
                uint32_t b1 = __float_as_uint(Vt[off + 4]);
                mma_tf32(O[0][n8], pa[0][0], pa[0][1], pa[0][2], pa[0][3], b0, b1);
                mma_tf32(O[1][n8], pa[1][0], pa[1][1], pa[1][2], pa[1][3], b0, b1);
            }
        }
    }

    // normalize + store (tf32-rounded for the proj GEMM)
    #pragma unroll
    for (int a = 0; a < 2; a++) {
        float l0 = l[a][0], l1 = l[a][1];
        l0 += __shfl_xor_sync(0xffffffffu, l0, 1);
        l0 += __shfl_xor_sync(0xffffffffu, l0, 2);
        l1 += __shfl_xor_sync(0xffffffffu, l1, 1);
        l1 += __shfl_xor_sync(0xffffffffu, l1, 2);
        const float i0 = 1.0f / l0;
        const float i1 = 1.0f / l1;

        float* ob = g_att + ((size_t)bb * T + (size_t)qt * 128 + warp * 32 + a * 16 + g) * C + h * 64;
        #pragma unroll
        for (int n8 = 0; n8 < 8; n8++) {
            *(float2*)&ob[n8 * 8 + 2 * t] =
                make_float2(f2tf32(O[a][n8].x * i0), f2tf32(O[a][n8].y * i0));
            *(float2*)&ob[8 * C + n8 * 8 + 2 * t] =
                make_float2(f2tf32(O[a][n8].z * i1), f2tf32(O[a][n8].w * i1));
        }
    }
}

// ---------------------------------------------------------------------------
extern "C" void kernel_launch(void* const* d_in, const int* in_sizes, int n_in,
                              void* d_out, int out_size)
{
    const float* x  = (const float*)d_in[0];
    const float* Wq = (const float*)d_in[1];
    const float* bq = (const float*)d_in[2];
    const float* Wk = (const float*)d_in[3];
    const float* bk = (const float*)d_in[4];
    const float* Wv = (const float*)d_in[5];
    const float* bv = (const float*)d_in[6];
    const float* Wp = (const float*)d_in[7];
    const float* bp = (const float*)d_in[8];
    float* out = (float*)d_out;

    const int GEMM_SMEM = 3 * STAGE_FLOATS * sizeof(float);   // 107520 B
    const int ATTN_SMEM = 3 * 8704 * sizeof(float);           // 104448 B

    cudaFuncSetAttribute(gemm_tc<1>, cudaFuncAttributeMaxDynamicSharedMemorySize, GEMM_SMEM);
    cudaFuncSetAttribute(gemm_tc<0>, cudaFuncAttributeMaxDynamicSharedMemorySize, GEMM_SMEM);
    cudaFuncSetAttribute(attn_tc,    cudaFuncAttributeMaxDynamicSharedMemorySize, ATTN_SMEM);

    cvt_all<<<12288, 256>>>(x, Wq, Wk, Wv, Wp);

    dim3 gq(24, M / 128);   // fused QKV
    gemm_tc<1><<<gq, 256, GEMM_SMEM>>>(bq, bk, bv, nullptr);

    dim3 ga(T / 128, NH, Bz);   // 16 x 16 x 4
    attn_tc<<<ga, 128, ATTN_SMEM>>>();

    dim3 gp(8, M / 128);
    gemm_tc<0><<<gp, 256, GEMM_SMEM>>>(bp, nullptr, nullptr, out);
}